// round 12
// baseline (speedup 1.0000x reference)
#include <cuda_runtime.h>
#include <cuda_bf16.h>
#include <math.h>
#include <stdint.h>

#define N_NODES 50000
#define N_GRAPHS 512
#define FC 128
#define NCLS 2
#define EMAX 2000000
#define NBLK 391   // ceil(N_NODES/128)

// ---------------- scratch (device globals; no allocs allowed) ----------------
// Self-cleaning invariant: g_cnt, g_psum, g_pcnt are zero at entry of every
// kernel_launch call (zero-initialized at load; re-zeroed by their consumers).
__device__ float g_h1[(size_t)N_NODES * FC];
__device__ float g_h2[(size_t)N_NODES * FC];
// agg stored as pre-swizzled, hi/lo-split bf16 SMEM images: [NBLK][2 chunks][8192]
__device__ __nv_bfloat16 g_agb_hi[(size_t)NBLK * 2 * 8192];
__device__ __nv_bfloat16 g_agb_lo[(size_t)NBLK * 2 * 8192];
__device__ int   g_cnt[N_NODES];
__device__ int   g_off[N_NODES + 1];
__device__ int   g_cur[N_NODES];
__device__ int   g_csr[EMAX];
__device__ float g_psum[N_GRAPHS * FC];
__device__ int   g_pcnt[N_GRAPHS];
// pre-transposed, hi/lo-split, pre-swizzled weights: [3 layers][4 chunks][8192 bf16]
__device__ __nv_bfloat16 g_bt_hi[3 * 4 * 8192];
__device__ __nv_bfloat16 g_bt_lo[3 * 4 * 8192];

#define SWZ128(b) ((b) ^ (((b) >> 3) & 0x70))

__device__ __forceinline__ uint32_t smem_to_u32(const void* p) {
    uint32_t a;
    asm("{ .reg .u64 t; cvta.to.shared.u64 t, %1; cvt.u32.u64 %0, t; }" : "=r"(a) : "l"(p));
    return a;
}
__device__ __forceinline__ void ldsm4(uint32_t& r0, uint32_t& r1, uint32_t& r2, uint32_t& r3,
                                      uint32_t addr) {
    asm volatile("ldmatrix.sync.aligned.m8n8.x4.shared.b16 {%0,%1,%2,%3}, [%4];"
                 : "=r"(r0), "=r"(r1), "=r"(r2), "=r"(r3) : "r"(addr));
}
__device__ __forceinline__ void mma16816(float* d, const uint32_t* a, uint32_t b0, uint32_t b1) {
    asm volatile(
        "mma.sync.aligned.m16n8k16.row.col.f32.bf16.bf16.f32 "
        "{%0,%1,%2,%3}, {%4,%5,%6,%7}, {%8,%9}, {%0,%1,%2,%3};"
        : "+f"(d[0]), "+f"(d[1]), "+f"(d[2]), "+f"(d[3])
        : "r"(a[0]), "r"(a[1]), "r"(a[2]), "r"(a[3]), "r"(b0), "r"(b1));
}
// packed f32x2 add (base Blackwell PTX; NOT an 'a'-gated feature)
__device__ __forceinline__ void addf32x2(unsigned long long& a, unsigned long long b) {
    asm("add.rn.f32x2 %0, %1, %2;" : "=l"(a) : "l"(a), "l"(b));
}

// ---------------- degree ----------------
__global__ void degree_kernel(const int* __restrict__ ei, int E) {
    int e = blockIdx.x * blockDim.x + threadIdx.x;
    if (e < E) atomicAdd(&g_cnt[ei[E + e]], 1);
}

// ---------------- exclusive scan over g_cnt -> g_off/g_cur; re-zeroes g_cnt ----
__global__ void __launch_bounds__(1024) scan_kernel() {
    __shared__ int wsum[32];
    __shared__ int s_carry;
    const int tid = threadIdx.x, lane = tid & 31, wid = tid >> 5;
    if (tid == 0) s_carry = 0;
    __syncthreads();
    for (int base = 0; base < N_NODES; base += 4096) {
        int i0 = base + tid * 4;
        int4 c = make_int4(0, 0, 0, 0);
        if (i0 + 3 < N_NODES) c = *reinterpret_cast<int4*>(&g_cnt[i0]);
        int t1 = c.x + c.y;
        int t2 = t1 + c.z;
        int tot = t2 + c.w;
        int v = tot;
#pragma unroll
        for (int o = 1; o < 32; o <<= 1) {
            int t = __shfl_up_sync(0xffffffffu, v, o);
            if (lane >= o) v += t;
        }
        if (lane == 31) wsum[wid] = v;
        __syncthreads();
        if (wid == 0) {
            int s = wsum[lane];
            int so = s;
#pragma unroll
            for (int o = 1; o < 32; o <<= 1) {
                int t = __shfl_up_sync(0xffffffffu, s, o);
                if (lane >= o) s += t;
            }
            wsum[lane] = s - so;
        }
        __syncthreads();
        int incl = v + wsum[wid];
        int carry = s_carry;
        if (i0 + 3 < N_NODES) {
            int e0 = carry + incl - tot;
            int4 off = make_int4(e0, e0 + c.x, e0 + t1, e0 + t2);
            *reinterpret_cast<int4*>(&g_off[i0]) = off;
            *reinterpret_cast<int4*>(&g_cur[i0]) = off;
            *reinterpret_cast<int4*>(&g_cnt[i0]) = make_int4(0, 0, 0, 0);  // self-clean
        }
        __syncthreads();
        if (tid == 1023) s_carry = carry + incl;
        __syncthreads();
    }
    if (tid == 0) g_off[N_NODES] = s_carry;
}

__global__ void csr_fill_kernel(const int* __restrict__ ei, int E) {
    int e = blockIdx.x * blockDim.x + threadIdx.x;
    if (e >= E) return;
    int dst = __ldg(&ei[E + e]);
    int pos = atomicAdd(&g_cur[dst], 1);
    g_csr[pos] = __ldg(&ei[e]);
}

// ---------------- gather: mean over neighbors (warp/node, f32x2 packed adds);
//                  writes split-bf16 pre-swizzled agg images directly ----------
__global__ void __launch_bounds__(256) gather_kernel(const float* __restrict__ x) {
    int w = (blockIdx.x * blockDim.x + threadIdx.x) >> 5;
    int lane = threadIdx.x & 31;
    if (w >= N_NODES) return;
    const int beg = g_off[w];
    const int end = g_off[w + 1];
    unsigned long long A0 = 0ull, B0 = 0ull, A1 = 0ull, B1 = 0ull;
    for (int base = beg; base < end; base += 32) {
        int idx = base + lane;
        int si = (idx < end) ? g_csr[idx] : 0;
        int m = end - base;
        if (m >= 32) {
#pragma unroll 4
            for (int j = 0; j < 32; j += 2) {
                int s0 = __shfl_sync(0xffffffffu, si, j);
                int s1 = __shfl_sync(0xffffffffu, si, j + 1);
                ulonglong2 u0 = __ldg(
                    reinterpret_cast<const ulonglong2*>(x + (size_t)s0 * FC) + lane);
                ulonglong2 u1 = __ldg(
                    reinterpret_cast<const ulonglong2*>(x + (size_t)s1 * FC) + lane);
                addf32x2(A0, u0.x); addf32x2(B0, u0.y);
                addf32x2(A1, u1.x); addf32x2(B1, u1.y);
            }
        } else {
            int j = 0;
            for (; j + 1 < m; j += 2) {
                int s0 = __shfl_sync(0xffffffffu, si, j);
                int s1 = __shfl_sync(0xffffffffu, si, j + 1);
                ulonglong2 u0 = __ldg(
                    reinterpret_cast<const ulonglong2*>(x + (size_t)s0 * FC) + lane);
                ulonglong2 u1 = __ldg(
                    reinterpret_cast<const ulonglong2*>(x + (size_t)s1 * FC) + lane);
                addf32x2(A0, u0.x); addf32x2(B0, u0.y);
                addf32x2(A1, u1.x); addf32x2(B1, u1.y);
            }
            if (j < m) {
                int s0 = __shfl_sync(0xffffffffu, si, j);
                ulonglong2 u0 = __ldg(
                    reinterpret_cast<const ulonglong2*>(x + (size_t)s0 * FC) + lane);
                addf32x2(A0, u0.x); addf32x2(B0, u0.y);
            }
        }
    }
    addf32x2(A0, A1);
    addf32x2(B0, B1);
    float2 f01 = *reinterpret_cast<float2*>(&A0);
    float2 f23 = *reinterpret_cast<float2*>(&B0);
    float inv = 1.f / fmaxf((float)(end - beg), 1.f);
    float v0 = f01.x * inv;
    float v1 = f01.y * inv;
    float v2 = f23.x * inv;
    float v3 = f23.y * inv;
    // split to bf16 hi/lo and store into the pre-swizzled SMEM image
    __nv_bfloat16 h0 = __float2bfloat16(v0);
    __nv_bfloat16 h1 = __float2bfloat16(v1);
    __nv_bfloat16 h2 = __float2bfloat16(v2);
    __nv_bfloat16 h3 = __float2bfloat16(v3);
    __nv_bfloat162 hh[2] = {__nv_bfloat162(h0, h1), __nv_bfloat162(h2, h3)};
    __nv_bfloat162 ll[2] = {
        __nv_bfloat162(__float2bfloat16(v0 - __bfloat162float(h0)),
                       __float2bfloat16(v1 - __bfloat162float(h1))),
        __nv_bfloat162(__float2bfloat16(v2 - __bfloat162float(h2)),
                       __float2bfloat16(v3 - __bfloat162float(h3)))};
    int blk = w >> 7, r = w & 127;
    int c = lane >> 4;              // chunk (cols 0-63 / 64-127)
    int kk = (lane & 15) * 4;       // col within chunk
    int swz = SWZ128(r * 128 + kk * 2);
    size_t img = ((size_t)blk * 2 + c) * 16384;  // bytes
    *reinterpret_cast<uint2*>(reinterpret_cast<char*>(g_agb_hi) + img + swz) =
        *reinterpret_cast<uint2*>(hh);
    *reinterpret_cast<uint2*>(reinterpret_cast<char*>(g_agb_lo) + img + swz) =
        *reinterpret_cast<uint2*>(ll);
}

// ---------------- weight prep: all 3 layers, transpose + split + swizzle -------
__global__ void prep_weights_all_kernel(
    const float* __restrict__ w1l, const float* __restrict__ w1r,
    const float* __restrict__ w2l, const float* __restrict__ w2r,
    const float* __restrict__ w3l, const float* __restrict__ w3r)
{
    int idx = blockIdx.x * blockDim.x + threadIdx.x;  // 3*32768
    int layer = idx >> 15;
    int li = idx & 32767;
    int n = li >> 8, k = li & 255;
    const float* wl = (layer == 0) ? w1l : (layer == 1) ? w2l : w3l;
    const float* wr = (layer == 0) ? w1r : (layer == 1) ? w2r : w3r;
    float w = (k < 128) ? wl[k * FC + n] : wr[(k - 128) * FC + n];
    __nv_bfloat16 h = __float2bfloat16(w);
    __nv_bfloat16 l = __float2bfloat16(w - __bfloat162float(h));
    int chunk = k >> 6, kk = k & 63;
    int swz = SWZ128(n * 128 + kk * 2);
    g_bt_hi[layer * 32768 + chunk * 8192 + (swz >> 1)] = h;
    g_bt_lo[layer * 32768 + chunk * 8192 + (swz >> 1)] = l;
}

// ---------------- tensor-core fused layer (mma.sync bf16, split hi/lo) --------
#define SM_AHI 0
#define SM_ALO 16384
#define SM_BHI 32768
#define SM_BLO 49152
#define SM_PS  65536
#define SM_PQ  (SM_PS + 1024)
#define SM_TOTAL (SM_PQ + 1024)

template <bool RESID, bool POOL>
__global__ void __launch_bounds__(256) sage_mma_kernel(
    const float* __restrict__ xin,
    const float* __restrict__ bias, const float* __restrict__ gam,
    const float* __restrict__ bet,
    float* __restrict__ hout,
    const int* __restrict__ batch,
    int layer)
{
    extern __shared__ char smem[];
    const uint32_t sb = smem_to_u32(smem);
    const int tid = threadIdx.x;
    const int lane = tid & 31;
    const int wid = tid >> 5;
    const int wm = wid & 3;
    const int wn = wid >> 2;
    const int row0 = blockIdx.x * 128;

    float d[2][8][4];
#pragma unroll
    for (int i = 0; i < 2; i++)
#pragma unroll
        for (int j = 0; j < 8; j++)
#pragma unroll
            for (int t = 0; t < 4; t++) d[i][j][t] = 0.f;

    const int lm = lane >> 3, lr = lane & 7;
    int a_rowb[2];
#pragma unroll
    for (int mi = 0; mi < 2; mi++)
        a_rowb[mi] = (wm * 32 + mi * 16 + (lm & 1) * 8 + lr) * 128 + (lm >> 1) * 16;
    int b_rowb[4];
#pragma unroll
    for (int np = 0; np < 4; np++)
        b_rowb[np] = (wn * 64 + np * 16 + (lm >> 1) * 8 + lr) * 128 + (lm & 1) * 16;

    const __nv_bfloat16* btH = g_bt_hi + layer * 32768;
    const __nv_bfloat16* btL = g_bt_lo + layer * 32768;

    for (int chunk = 0; chunk < 4; chunk++) {
        if (chunk < 2) {
            // ---- agg chunk: straight copy of pre-split, pre-swizzled image ----
            const uint4* ah = reinterpret_cast<const uint4*>(
                g_agb_hi + ((size_t)blockIdx.x * 2 + chunk) * 8192);
            const uint4* al = reinterpret_cast<const uint4*>(
                g_agb_lo + ((size_t)blockIdx.x * 2 + chunk) * 8192);
            uint4* dh = reinterpret_cast<uint4*>(smem + SM_AHI);
            uint4* dl = reinterpret_cast<uint4*>(smem + SM_ALO);
#pragma unroll
            for (int it = 0; it < 4; it++) {
                int i = it * 256 + tid;
                dh[i] = __ldg(ah + i);
                dl[i] = __ldg(al + i);
            }
        } else {
            // ---- xin chunk: load fp32, split to bf16 hi/lo, swizzle ----
            const int kofs = (chunk & 1) * 64;
#pragma unroll
            for (int it = 0; it < 4; it++) {
                int idx = it * 256 + tid;       // 0..1023
                int r = idx >> 3;
                int kk0 = (idx & 7) * 8;
                int gr = row0 + r;
                float4 fa = make_float4(0.f, 0.f, 0.f, 0.f), fb = fa;
                if (gr < N_NODES) {
                    const float4* p = reinterpret_cast<const float4*>(
                        xin + (size_t)gr * FC + kofs + kk0);
                    fa = p[0]; fb = p[1];
                }
                float v[8] = {fa.x, fa.y, fa.z, fa.w, fb.x, fb.y, fb.z, fb.w};
                __nv_bfloat162 hh[4], ll[4];
#pragma unroll
                for (int j = 0; j < 4; j++) {
                    __nv_bfloat16 h0 = __float2bfloat16(v[2 * j]);
                    __nv_bfloat16 h1 = __float2bfloat16(v[2 * j + 1]);
                    __nv_bfloat16 l0 = __float2bfloat16(v[2 * j] - __bfloat162float(h0));
                    __nv_bfloat16 l1 = __float2bfloat16(v[2 * j + 1] - __bfloat162float(h1));
                    hh[j] = __nv_bfloat162(h0, h1);
                    ll[j] = __nv_bfloat162(l0, l1);
                }
                int swz = SWZ128(r * 128 + kk0 * 2);
                *reinterpret_cast<uint4*>(smem + SM_AHI + swz) = *reinterpret_cast<uint4*>(hh);
                *reinterpret_cast<uint4*>(smem + SM_ALO + swz) = *reinterpret_cast<uint4*>(ll);
            }
        }
        // ---- copy pre-swizzled B chunk ----
        {
            const uint4* bh = reinterpret_cast<const uint4*>(btH + chunk * 8192);
            const uint4* bl = reinterpret_cast<const uint4*>(btL + chunk * 8192);
            uint4* dh = reinterpret_cast<uint4*>(smem + SM_BHI);
            uint4* dl = reinterpret_cast<uint4*>(smem + SM_BLO);
#pragma unroll
            for (int it = 0; it < 4; it++) {
                int i = it * 256 + tid;
                dh[i] = __ldg(bh + i);
                dl[i] = __ldg(bl + i);
            }
        }
        __syncthreads();

#pragma unroll
        for (int ks = 0; ks < 4; ks++) {
            uint32_t ah[2][4], al[2][4];
#pragma unroll
            for (int mi = 0; mi < 2; mi++) {
                uint32_t off = SWZ128(a_rowb[mi] + ks * 32);
                ldsm4(ah[mi][0], ah[mi][1], ah[mi][2], ah[mi][3], sb + SM_AHI + off);
                ldsm4(al[mi][0], al[mi][1], al[mi][2], al[mi][3], sb + SM_ALO + off);
            }
#pragma unroll
            for (int np = 0; np < 4; np++) {
                uint32_t off = SWZ128(b_rowb[np] + ks * 32);
                uint32_t bh0, bh1, bh2, bh3, bl0, bl1, bl2, bl3;
                ldsm4(bh0, bh1, bh2, bh3, sb + SM_BHI + off);
                ldsm4(bl0, bl1, bl2, bl3, sb + SM_BLO + off);
#pragma unroll
                for (int mi = 0; mi < 2; mi++) {
                    mma16816(d[mi][np * 2 + 0], ah[mi], bh0, bh1);
                    mma16816(d[mi][np * 2 + 0], ah[mi], bl0, bl1);
                    mma16816(d[mi][np * 2 + 0], al[mi], bh0, bh1);
                    mma16816(d[mi][np * 2 + 1], ah[mi], bh2, bh3);
                    mma16816(d[mi][np * 2 + 1], ah[mi], bl2, bl3);
                    mma16816(d[mi][np * 2 + 1], al[mi], bh2, bh3);
                }
            }
        }
        __syncthreads();
    }

    // ---------- epilogue: bias, relu, residual, LayerNorm (+ pool) ----------
    const int cb = wn * 64 + (lane & 3) * 2;
    float2 bb[8];
#pragma unroll
    for (int ni = 0; ni < 8; ni++)
        bb[ni] = __ldg(reinterpret_cast<const float2*>(bias + cb + ni * 8));

    float s[2][2] = {{0.f, 0.f}, {0.f, 0.f}};
    float q[2][2] = {{0.f, 0.f}, {0.f, 0.f}};
#pragma unroll
    for (int mi = 0; mi < 2; mi++) {
#pragma unroll
        for (int z = 0; z < 2; z++) {
            int rl = wm * 32 + mi * 16 + z * 8 + (lane >> 2);
            int gr = row0 + rl;
            bool valid = gr < N_NODES;
#pragma unroll
            for (int ni = 0; ni < 8; ni++) {
                float2 rv = make_float2(0.f, 0.f);
                if (RESID && valid)
                    rv = *reinterpret_cast<const float2*>(xin + (size_t)gr * FC + cb + ni * 8);
                float v0 = fmaxf(d[mi][ni][z * 2 + 0] + bb[ni].x, 0.f) + rv.x;
                float v1 = fmaxf(d[mi][ni][z * 2 + 1] + bb[ni].y, 0.f) + rv.y;
                s[mi][z] += v0 + v1;
                q[mi][z] += v0 * v0 + v1 * v1;
                d[mi][ni][z * 2 + 0] = v0;
                d[mi][ni][z * 2 + 1] = v1;
            }
        }
    }
    float* ps = reinterpret_cast<float*>(smem + SM_PS);
    float* pq = reinterpret_cast<float*>(smem + SM_PQ);
#pragma unroll
    for (int mi = 0; mi < 2; mi++) {
#pragma unroll
        for (int z = 0; z < 2; z++) {
            float ss = s[mi][z], qq = q[mi][z];
            ss += __shfl_xor_sync(0xffffffffu, ss, 1);
            ss += __shfl_xor_sync(0xffffffffu, ss, 2);
            qq += __shfl_xor_sync(0xffffffffu, qq, 1);
            qq += __shfl_xor_sync(0xffffffffu, qq, 2);
            if ((lane & 3) == 0) {
                int rl = wm * 32 + mi * 16 + z * 8 + (lane >> 2);
                ps[wn * 128 + rl] = ss;
                pq[wn * 128 + rl] = qq;
            }
        }
    }
    __syncthreads();
#pragma unroll
    for (int mi = 0; mi < 2; mi++) {
#pragma unroll
        for (int z = 0; z < 2; z++) {
            int rl = wm * 32 + mi * 16 + z * 8 + (lane >> 2);
            int gr = row0 + rl;
            if (gr >= N_NODES) continue;
            float S = ps[rl] + ps[128 + rl];
            float Q = pq[rl] + pq[128 + rl];
            float mean = S * (1.f / 128.f);
            float var = Q * (1.f / 128.f) - mean * mean;
            float rs = rsqrtf(var + 1e-5f);
            int bgr = POOL ? __ldg(&batch[gr]) : 0;
#pragma unroll
            for (int ni = 0; ni < 8; ni++) {
                float2 g2 = __ldg(reinterpret_cast<const float2*>(gam + cb + ni * 8));
                float2 e2 = __ldg(reinterpret_cast<const float2*>(bet + cb + ni * 8));
                float2 o2;
                o2.x = (d[mi][ni][z * 2 + 0] - mean) * rs * g2.x + e2.x;
                o2.y = (d[mi][ni][z * 2 + 1] - mean) * rs * g2.y + e2.y;
                *reinterpret_cast<float2*>(hout + (size_t)gr * FC + cb + ni * 8) = o2;
                if (POOL) {
                    atomicAdd(&g_psum[bgr * FC + cb + ni * 8], o2.x);
                    atomicAdd(&g_psum[bgr * FC + cb + ni * 8 + 1], o2.y);
                }
            }
            if (POOL && wn == 0 && (lane & 3) == 0)
                atomicAdd(&g_pcnt[bgr], 1);
        }
    }
}

// ---------------- finalize: avg + classifier; self-cleans g_psum/g_pcnt --------
__global__ void pool_finalize_kernel(const float* __restrict__ wc, const float* __restrict__ bc,
                                     float* __restrict__ logits, float* __restrict__ avg_out) {
    int g = blockIdx.x;
    int lane = threadIdx.x;  // blockDim = 32
    float inv = 1.f / fmaxf((float)g_pcnt[g], 1.f);
    float4 v = *reinterpret_cast<const float4*>(g_psum + g * FC + lane * 4);
    *reinterpret_cast<float4*>(g_psum + g * FC + lane * 4) = make_float4(0.f, 0.f, 0.f, 0.f);
    if (lane == 0) g_pcnt[g] = 0;
    v.x *= inv; v.y *= inv; v.z *= inv; v.w *= inv;
    *reinterpret_cast<float4*>(avg_out + (size_t)g * FC + lane * 4) = v;
    int c = lane * 4;
    float s0 = v.x * wc[(c + 0) * NCLS + 0] + v.y * wc[(c + 1) * NCLS + 0] +
               v.z * wc[(c + 2) * NCLS + 0] + v.w * wc[(c + 3) * NCLS + 0];
    float s1 = v.x * wc[(c + 0) * NCLS + 1] + v.y * wc[(c + 1) * NCLS + 1] +
               v.z * wc[(c + 2) * NCLS + 1] + v.w * wc[(c + 3) * NCLS + 1];
#pragma unroll
    for (int o = 16; o > 0; o >>= 1) {
        s0 += __shfl_xor_sync(0xffffffffu, s0, o);
        s1 += __shfl_xor_sync(0xffffffffu, s1, o);
    }
    if (lane == 0) {
        logits[g * NCLS + 0] = s0 + bc[0];
        logits[g * NCLS + 1] = s1 + bc[1];
    }
}

// ---------------- launch ----------------
extern "C" void kernel_launch(void* const* d_in, const int* in_sizes, int n_in,
                              void* d_out, int out_size) {
    const float* x     = (const float*)d_in[0];
    const int*   ei    = (const int*)d_in[1];
    const int*   batch = (const int*)d_in[2];
    const float* w1l = (const float*)d_in[3];
    const float* w1r = (const float*)d_in[4];
    const float* b1  = (const float*)d_in[5];
    const float* g1  = (const float*)d_in[6];
    const float* be1 = (const float*)d_in[7];
    const float* w2l = (const float*)d_in[8];
    const float* w2r = (const float*)d_in[9];
    const float* b2  = (const float*)d_in[10];
    const float* g2  = (const float*)d_in[11];
    const float* be2 = (const float*)d_in[12];
    const float* w3l = (const float*)d_in[13];
    const float* w3r = (const float*)d_in[14];
    const float* b3  = (const float*)d_in[15];
    const float* g3  = (const float*)d_in[16];
    const float* be3 = (const float*)d_in[17];
    const float* wc  = (const float*)d_in[18];
    const float* bc  = (const float*)d_in[19];

    const int E = in_sizes[1] / 2;

    float* out    = (float*)d_out;
    float* logits = out;
    float* h3     = out + (size_t)N_GRAPHS * NCLS;
    float* avg    = h3 + (size_t)N_NODES * FC;

    float *p_h1 = nullptr, *p_h2 = nullptr;
    cudaGetSymbolAddress((void**)&p_h1, g_h1);
    cudaGetSymbolAddress((void**)&p_h2, g_h2);

    cudaFuncSetAttribute(sage_mma_kernel<false, false>,
                         cudaFuncAttributeMaxDynamicSharedMemorySize, SM_TOTAL);
    cudaFuncSetAttribute(sage_mma_kernel<true, false>,
                         cudaFuncAttributeMaxDynamicSharedMemorySize, SM_TOTAL);
    cudaFuncSetAttribute(sage_mma_kernel<true, true>,
                         cudaFuncAttributeMaxDynamicSharedMemorySize, SM_TOTAL);

    const int TC_BLKS = NBLK;  // 391
    const int NODE_WARP_BLKS = (int)(((size_t)N_NODES * 32 + 255) / 256);
    const int EDGE_BLKS = (E + 255) / 256;

    // CSR build (g_cnt is zero on entry; scan re-zeroes it) + weight prep
    degree_kernel<<<EDGE_BLKS, 256>>>(ei, E);
    scan_kernel<<<1, 1024>>>();
    csr_fill_kernel<<<EDGE_BLKS, 256>>>(ei, E);
    prep_weights_all_kernel<<<384, 256>>>(w1l, w1r, w2l, w2r, w3l, w3r);

    // layer 1
    gather_kernel<<<NODE_WARP_BLKS, 256>>>(x);
    sage_mma_kernel<false, false><<<TC_BLKS, 256, SM_TOTAL>>>(
        x, b1, g1, be1, p_h1, batch, 0);

    // layer 2 (residual)
    gather_kernel<<<NODE_WARP_BLKS, 256>>>(p_h1);
    sage_mma_kernel<true, false><<<TC_BLKS, 256, SM_TOTAL>>>(
        p_h1, b2, g2, be2, p_h2, batch, 1);

    // layer 3 (residual + pool) -> h3 straight into d_out
    gather_kernel<<<NODE_WARP_BLKS, 256>>>(p_h2);
    sage_mma_kernel<true, true><<<TC_BLKS, 256, SM_TOTAL>>>(
        p_h2, b3, g3, be3, h3, batch, 2);

    pool_finalize_kernel<<<N_GRAPHS, 32>>>(wc, bc, logits, avg);
}

// round 13
// speedup vs baseline: 1.0499x; 1.0499x over previous
#include <cuda_runtime.h>
#include <cuda_bf16.h>
#include <math.h>
#include <stdint.h>

#define N_NODES 50000
#define N_GRAPHS 512
#define FC 128
#define NCLS 2
#define EMAX 2000000
#define NBLK 391   // ceil(N_NODES/128)

// ---------------- scratch (device globals; no allocs allowed) ----------------
// Self-cleaning invariant: g_cnt, g_psum, g_pcnt are zero at entry of every
// kernel_launch call (zero-initialized at load; re-zeroed by their consumers).
__device__ float g_h1[(size_t)N_NODES * FC];
__device__ float g_h2[(size_t)N_NODES * FC];
// agg stored as pre-swizzled, hi/lo-split bf16 SMEM images: [NBLK][2 chunks][8192]
__device__ __nv_bfloat16 g_agb_hi[(size_t)NBLK * 2 * 8192];
__device__ __nv_bfloat16 g_agb_lo[(size_t)NBLK * 2 * 8192];
__device__ int   g_cnt[N_NODES];
__device__ int   g_off[N_NODES + 1];
__device__ int   g_cur[N_NODES];
__device__ int   g_csr[EMAX];
__device__ float g_psum[N_GRAPHS * FC];
__device__ int   g_pcnt[N_GRAPHS];
// pre-transposed, hi/lo-split, pre-swizzled weights: [3 layers][4 chunks][8192 bf16]
__device__ __nv_bfloat16 g_bt_hi[3 * 4 * 8192];
__device__ __nv_bfloat16 g_bt_lo[3 * 4 * 8192];

#define SWZ128(b) ((b) ^ (((b) >> 3) & 0x70))

__device__ __forceinline__ uint32_t smem_to_u32(const void* p) {
    uint32_t a;
    asm("{ .reg .u64 t; cvta.to.shared.u64 t, %1; cvt.u32.u64 %0, t; }" : "=r"(a) : "l"(p));
    return a;
}
__device__ __forceinline__ void ldsm4(uint32_t& r0, uint32_t& r1, uint32_t& r2, uint32_t& r3,
                                      uint32_t addr) {
    asm volatile("ldmatrix.sync.aligned.m8n8.x4.shared.b16 {%0,%1,%2,%3}, [%4];"
                 : "=r"(r0), "=r"(r1), "=r"(r2), "=r"(r3) : "r"(addr));
}
__device__ __forceinline__ void mma16816(float* d, const uint32_t* a, uint32_t b0, uint32_t b1) {
    asm volatile(
        "mma.sync.aligned.m16n8k16.row.col.f32.bf16.bf16.f32 "
        "{%0,%1,%2,%3}, {%4,%5,%6,%7}, {%8,%9}, {%0,%1,%2,%3};"
        : "+f"(d[0]), "+f"(d[1]), "+f"(d[2]), "+f"(d[3])
        : "r"(a[0]), "r"(a[1]), "r"(a[2]), "r"(a[3]), "r"(b0), "r"(b1));
}

// ---------------- degree + weight prep (fused; prep covers first 98304 threads)
__global__ void degree_prep_kernel(
    const int* __restrict__ ei, int E,
    const float* __restrict__ w1l, const float* __restrict__ w1r,
    const float* __restrict__ w2l, const float* __restrict__ w2r,
    const float* __restrict__ w3l, const float* __restrict__ w3r)
{
    int i = blockIdx.x * blockDim.x + threadIdx.x;
    if (i < E) atomicAdd(&g_cnt[ei[E + i]], 1);
    if (i < 3 * 32768) {
        int layer = i >> 15;
        int li = i & 32767;
        int n = li >> 8, k = li & 255;
        const float* wl = (layer == 0) ? w1l : (layer == 1) ? w2l : w3l;
        const float* wr = (layer == 0) ? w1r : (layer == 1) ? w2r : w3r;
        float w = (k < 128) ? wl[k * FC + n] : wr[(k - 128) * FC + n];
        __nv_bfloat16 h = __float2bfloat16(w);
        __nv_bfloat16 l = __float2bfloat16(w - __bfloat162float(h));
        int chunk = k >> 6, kk = k & 63;
        int swz = SWZ128(n * 128 + kk * 2);
        g_bt_hi[layer * 32768 + chunk * 8192 + (swz >> 1)] = h;
        g_bt_lo[layer * 32768 + chunk * 8192 + (swz >> 1)] = l;
    }
}

// ---------------- exclusive scan over g_cnt -> g_off/g_cur; re-zeroes g_cnt ----
__global__ void __launch_bounds__(1024) scan_kernel() {
    __shared__ int wsum[32];
    __shared__ int s_carry;
    const int tid = threadIdx.x, lane = tid & 31, wid = tid >> 5;
    if (tid == 0) s_carry = 0;
    __syncthreads();
    for (int base = 0; base < N_NODES; base += 4096) {
        int i0 = base + tid * 4;
        int4 c = make_int4(0, 0, 0, 0);
        if (i0 + 3 < N_NODES) c = *reinterpret_cast<int4*>(&g_cnt[i0]);
        int t1 = c.x + c.y;
        int t2 = t1 + c.z;
        int tot = t2 + c.w;
        int v = tot;
#pragma unroll
        for (int o = 1; o < 32; o <<= 1) {
            int t = __shfl_up_sync(0xffffffffu, v, o);
            if (lane >= o) v += t;
        }
        if (lane == 31) wsum[wid] = v;
        __syncthreads();
        if (wid == 0) {
            int s = wsum[lane];
            int so = s;
#pragma unroll
            for (int o = 1; o < 32; o <<= 1) {
                int t = __shfl_up_sync(0xffffffffu, s, o);
                if (lane >= o) s += t;
            }
            wsum[lane] = s - so;
        }
        __syncthreads();
        int incl = v + wsum[wid];
        int carry = s_carry;
        if (i0 + 3 < N_NODES) {
            int e0 = carry + incl - tot;
            int4 off = make_int4(e0, e0 + c.x, e0 + t1, e0 + t2);
            *reinterpret_cast<int4*>(&g_off[i0]) = off;
            *reinterpret_cast<int4*>(&g_cur[i0]) = off;
            *reinterpret_cast<int4*>(&g_cnt[i0]) = make_int4(0, 0, 0, 0);  // self-clean
        }
        __syncthreads();
        if (tid == 1023) s_carry = carry + incl;
        __syncthreads();
    }
    if (tid == 0) g_off[N_NODES] = s_carry;
}

__global__ void csr_fill_kernel(const int* __restrict__ ei, int E) {
    int e = blockIdx.x * blockDim.x + threadIdx.x;
    if (e >= E) return;
    int dst = __ldg(&ei[E + e]);
    int pos = atomicAdd(&g_cur[dst], 1);
    g_csr[pos] = __ldg(&ei[e]);
}

// ---------------- gather: mean over neighbors (warp/node); writes split-bf16
//                  pre-swizzled agg images directly -------------------------
__global__ void __launch_bounds__(256) gather_kernel(const float* __restrict__ x) {
    int w = (blockIdx.x * blockDim.x + threadIdx.x) >> 5;
    int lane = threadIdx.x & 31;
    if (w >= N_NODES) return;
    const int beg = g_off[w];
    const int end = g_off[w + 1];
    float4 a0 = make_float4(0.f, 0.f, 0.f, 0.f);
    float4 a1 = make_float4(0.f, 0.f, 0.f, 0.f);
    for (int base = beg; base < end; base += 32) {
        int idx = base + lane;
        int si = (idx < end) ? g_csr[idx] : 0;
        int m = end - base;
        if (m >= 32) {
#pragma unroll 4
            for (int j = 0; j < 32; j += 2) {
                int s0 = __shfl_sync(0xffffffffu, si, j);
                int s1 = __shfl_sync(0xffffffffu, si, j + 1);
                float4 v0 = __ldg(reinterpret_cast<const float4*>(x + (size_t)s0 * FC) + lane);
                float4 v1 = __ldg(reinterpret_cast<const float4*>(x + (size_t)s1 * FC) + lane);
                a0.x += v0.x; a0.y += v0.y; a0.z += v0.z; a0.w += v0.w;
                a1.x += v1.x; a1.y += v1.y; a1.z += v1.z; a1.w += v1.w;
            }
        } else {
            int j = 0;
            for (; j + 1 < m; j += 2) {
                int s0 = __shfl_sync(0xffffffffu, si, j);
                int s1 = __shfl_sync(0xffffffffu, si, j + 1);
                float4 v0 = __ldg(reinterpret_cast<const float4*>(x + (size_t)s0 * FC) + lane);
                float4 v1 = __ldg(reinterpret_cast<const float4*>(x + (size_t)s1 * FC) + lane);
                a0.x += v0.x; a0.y += v0.y; a0.z += v0.z; a0.w += v0.w;
                a1.x += v1.x; a1.y += v1.y; a1.z += v1.z; a1.w += v1.w;
            }
            if (j < m) {
                int s0 = __shfl_sync(0xffffffffu, si, j);
                float4 v0 = __ldg(reinterpret_cast<const float4*>(x + (size_t)s0 * FC) + lane);
                a0.x += v0.x; a0.y += v0.y; a0.z += v0.z; a0.w += v0.w;
            }
        }
    }
    float inv = 1.f / fmaxf((float)(end - beg), 1.f);
    float v0 = (a0.x + a1.x) * inv;
    float v1 = (a0.y + a1.y) * inv;
    float v2 = (a0.z + a1.z) * inv;
    float v3 = (a0.w + a1.w) * inv;
    // split to bf16 hi/lo and store into the pre-swizzled SMEM image
    __nv_bfloat16 h0 = __float2bfloat16(v0);
    __nv_bfloat16 h1 = __float2bfloat16(v1);
    __nv_bfloat16 h2 = __float2bfloat16(v2);
    __nv_bfloat16 h3 = __float2bfloat16(v3);
    __nv_bfloat162 hh[2] = {__nv_bfloat162(h0, h1), __nv_bfloat162(h2, h3)};
    __nv_bfloat162 ll[2] = {
        __nv_bfloat162(__float2bfloat16(v0 - __bfloat162float(h0)),
                       __float2bfloat16(v1 - __bfloat162float(h1))),
        __nv_bfloat162(__float2bfloat16(v2 - __bfloat162float(h2)),
                       __float2bfloat16(v3 - __bfloat162float(h3)))};
    int blk = w >> 7, r = w & 127;
    int c = lane >> 4;              // chunk (cols 0-63 / 64-127)
    int kk = (lane & 15) * 4;       // col within chunk
    int swz = SWZ128(r * 128 + kk * 2);
    size_t img = ((size_t)blk * 2 + c) * 16384;  // bytes
    *reinterpret_cast<uint2*>(reinterpret_cast<char*>(g_agb_hi) + img + swz) =
        *reinterpret_cast<uint2*>(hh);
    *reinterpret_cast<uint2*>(reinterpret_cast<char*>(g_agb_lo) + img + swz) =
        *reinterpret_cast<uint2*>(ll);
}

// ---------------- tensor-core fused layer (mma.sync bf16, split hi/lo) --------
#define SM_AHI 0
#define SM_ALO 16384
#define SM_BHI 32768
#define SM_BLO 49152
#define SM_PS  65536
#define SM_PQ  (SM_PS + 1024)
#define SM_TOTAL (SM_PQ + 1024)

template <bool RESID, bool POOL>
__global__ void __launch_bounds__(256) sage_mma_kernel(
    const float* __restrict__ xin,
    const float* __restrict__ bias, const float* __restrict__ gam,
    const float* __restrict__ bet,
    float* __restrict__ hout,
    const int* __restrict__ batch,
    int layer)
{
    extern __shared__ char smem[];
    const uint32_t sb = smem_to_u32(smem);
    const int tid = threadIdx.x;
    const int lane = tid & 31;
    const int wid = tid >> 5;
    const int wm = wid & 3;
    const int wn = wid >> 2;
    const int row0 = blockIdx.x * 128;

    float d[2][8][4];
#pragma unroll
    for (int i = 0; i < 2; i++)
#pragma unroll
        for (int j = 0; j < 8; j++)
#pragma unroll
            for (int t = 0; t < 4; t++) d[i][j][t] = 0.f;

    const int lm = lane >> 3, lr = lane & 7;
    int a_rowb[2];
#pragma unroll
    for (int mi = 0; mi < 2; mi++)
        a_rowb[mi] = (wm * 32 + mi * 16 + (lm & 1) * 8 + lr) * 128 + (lm >> 1) * 16;
    int b_rowb[4];
#pragma unroll
    for (int np = 0; np < 4; np++)
        b_rowb[np] = (wn * 64 + np * 16 + (lm >> 1) * 8 + lr) * 128 + (lm & 1) * 16;

    const __nv_bfloat16* btH = g_bt_hi + layer * 32768;
    const __nv_bfloat16* btL = g_bt_lo + layer * 32768;

    for (int chunk = 0; chunk < 4; chunk++) {
        if (chunk < 2) {
            // ---- agg chunk: straight copy of pre-split, pre-swizzled image ----
            const uint4* ah = reinterpret_cast<const uint4*>(
                g_agb_hi + ((size_t)blockIdx.x * 2 + chunk) * 8192);
            const uint4* al = reinterpret_cast<const uint4*>(
                g_agb_lo + ((size_t)blockIdx.x * 2 + chunk) * 8192);
            uint4* dh = reinterpret_cast<uint4*>(smem + SM_AHI);
            uint4* dl = reinterpret_cast<uint4*>(smem + SM_ALO);
#pragma unroll
            for (int it = 0; it < 4; it++) {
                int i = it * 256 + tid;
                dh[i] = __ldg(ah + i);
                dl[i] = __ldg(al + i);
            }
        } else {
            // ---- xin chunk: load fp32, split to bf16 hi/lo, swizzle ----
            const int kofs = (chunk & 1) * 64;
#pragma unroll
            for (int it = 0; it < 4; it++) {
                int idx = it * 256 + tid;       // 0..1023
                int r = idx >> 3;
                int kk0 = (idx & 7) * 8;
                int gr = row0 + r;
                float4 fa = make_float4(0.f, 0.f, 0.f, 0.f), fb = fa;
                if (gr < N_NODES) {
                    const float4* p = reinterpret_cast<const float4*>(
                        xin + (size_t)gr * FC + kofs + kk0);
                    fa = p[0]; fb = p[1];
                }
                float v[8] = {fa.x, fa.y, fa.z, fa.w, fb.x, fb.y, fb.z, fb.w};
                __nv_bfloat162 hh[4], ll[4];
#pragma unroll
                for (int j = 0; j < 4; j++) {
                    __nv_bfloat16 h0 = __float2bfloat16(v[2 * j]);
                    __nv_bfloat16 h1 = __float2bfloat16(v[2 * j + 1]);
                    __nv_bfloat16 l0 = __float2bfloat16(v[2 * j] - __bfloat162float(h0));
                    __nv_bfloat16 l1 = __float2bfloat16(v[2 * j + 1] - __bfloat162float(h1));
                    hh[j] = __nv_bfloat162(h0, h1);
                    ll[j] = __nv_bfloat162(l0, l1);
                }
                int swz = SWZ128(r * 128 + kk0 * 2);
                *reinterpret_cast<uint4*>(smem + SM_AHI + swz) = *reinterpret_cast<uint4*>(hh);
                *reinterpret_cast<uint4*>(smem + SM_ALO + swz) = *reinterpret_cast<uint4*>(ll);
            }
        }
        // ---- copy pre-swizzled B chunk ----
        {
            const uint4* bh = reinterpret_cast<const uint4*>(btH + chunk * 8192);
            const uint4* bl = reinterpret_cast<const uint4*>(btL + chunk * 8192);
            uint4* dh = reinterpret_cast<uint4*>(smem + SM_BHI);
            uint4* dl = reinterpret_cast<uint4*>(smem + SM_BLO);
#pragma unroll
            for (int it = 0; it < 4; it++) {
                int i = it * 256 + tid;
                dh[i] = __ldg(bh + i);
                dl[i] = __ldg(bl + i);
            }
        }
        __syncthreads();

#pragma unroll
        for (int ks = 0; ks < 4; ks++) {
            uint32_t ah[2][4], al[2][4];
#pragma unroll
            for (int mi = 0; mi < 2; mi++) {
                uint32_t off = SWZ128(a_rowb[mi] + ks * 32);
                ldsm4(ah[mi][0], ah[mi][1], ah[mi][2], ah[mi][3], sb + SM_AHI + off);
                ldsm4(al[mi][0], al[mi][1], al[mi][2], al[mi][3], sb + SM_ALO + off);
            }
#pragma unroll
            for (int np = 0; np < 4; np++) {
                uint32_t off = SWZ128(b_rowb[np] + ks * 32);
                uint32_t bh0, bh1, bh2, bh3, bl0, bl1, bl2, bl3;
                ldsm4(bh0, bh1, bh2, bh3, sb + SM_BHI + off);
                ldsm4(bl0, bl1, bl2, bl3, sb + SM_BLO + off);
#pragma unroll
                for (int mi = 0; mi < 2; mi++) {
                    mma16816(d[mi][np * 2 + 0], ah[mi], bh0, bh1);
                    mma16816(d[mi][np * 2 + 0], ah[mi], bl0, bl1);
                    mma16816(d[mi][np * 2 + 0], al[mi], bh0, bh1);
                    mma16816(d[mi][np * 2 + 1], ah[mi], bh2, bh3);
                    mma16816(d[mi][np * 2 + 1], ah[mi], bl2, bl3);
                    mma16816(d[mi][np * 2 + 1], al[mi], bh2, bh3);
                }
            }
        }
        __syncthreads();
    }

    // ---------- epilogue: bias, relu, residual, LayerNorm (+ pool) ----------
    const int cb = wn * 64 + (lane & 3) * 2;
    float2 bb[8];
#pragma unroll
    for (int ni = 0; ni < 8; ni++)
        bb[ni] = __ldg(reinterpret_cast<const float2*>(bias + cb + ni * 8));

    float s[2][2] = {{0.f, 0.f}, {0.f, 0.f}};
    float q[2][2] = {{0.f, 0.f}, {0.f, 0.f}};
#pragma unroll
    for (int mi = 0; mi < 2; mi++) {
#pragma unroll
        for (int z = 0; z < 2; z++) {
            int rl = wm * 32 + mi * 16 + z * 8 + (lane >> 2);
            int gr = row0 + rl;
            bool valid = gr < N_NODES;
#pragma unroll
            for (int ni = 0; ni < 8; ni++) {
                float2 rv = make_float2(0.f, 0.f);
                if (RESID && valid)
                    rv = *reinterpret_cast<const float2*>(xin + (size_t)gr * FC + cb + ni * 8);
                float v0 = fmaxf(d[mi][ni][z * 2 + 0] + bb[ni].x, 0.f) + rv.x;
                float v1 = fmaxf(d[mi][ni][z * 2 + 1] + bb[ni].y, 0.f) + rv.y;
                s[mi][z] += v0 + v1;
                q[mi][z] += v0 * v0 + v1 * v1;
                d[mi][ni][z * 2 + 0] = v0;
                d[mi][ni][z * 2 + 1] = v1;
            }
        }
    }
    float* ps = reinterpret_cast<float*>(smem + SM_PS);
    float* pq = reinterpret_cast<float*>(smem + SM_PQ);
#pragma unroll
    for (int mi = 0; mi < 2; mi++) {
#pragma unroll
        for (int z = 0; z < 2; z++) {
            float ss = s[mi][z], qq = q[mi][z];
            ss += __shfl_xor_sync(0xffffffffu, ss, 1);
            ss += __shfl_xor_sync(0xffffffffu, ss, 2);
            qq += __shfl_xor_sync(0xffffffffu, qq, 1);
            qq += __shfl_xor_sync(0xffffffffu, qq, 2);
            if ((lane & 3) == 0) {
                int rl = wm * 32 + mi * 16 + z * 8 + (lane >> 2);
                ps[wn * 128 + rl] = ss;
                pq[wn * 128 + rl] = qq;
            }
        }
    }
    __syncthreads();
#pragma unroll
    for (int mi = 0; mi < 2; mi++) {
#pragma unroll
        for (int z = 0; z < 2; z++) {
            int rl = wm * 32 + mi * 16 + z * 8 + (lane >> 2);
            int gr = row0 + rl;
            if (gr >= N_NODES) continue;
            float S = ps[rl] + ps[128 + rl];
            float Q = pq[rl] + pq[128 + rl];
            float mean = S * (1.f / 128.f);
            float var = Q * (1.f / 128.f) - mean * mean;
            float rs = rsqrtf(var + 1e-5f);
            int bgr = POOL ? __ldg(&batch[gr]) : 0;
#pragma unroll
            for (int ni = 0; ni < 8; ni++) {
                float2 g2 = __ldg(reinterpret_cast<const float2*>(gam + cb + ni * 8));
                float2 e2 = __ldg(reinterpret_cast<const float2*>(bet + cb + ni * 8));
                float2 o2;
                o2.x = (d[mi][ni][z * 2 + 0] - mean) * rs * g2.x + e2.x;
                o2.y = (d[mi][ni][z * 2 + 1] - mean) * rs * g2.y + e2.y;
                *reinterpret_cast<float2*>(hout + (size_t)gr * FC + cb + ni * 8) = o2;
                if (POOL) {
                    atomicAdd(&g_psum[bgr * FC + cb + ni * 8], o2.x);
                    atomicAdd(&g_psum[bgr * FC + cb + ni * 8 + 1], o2.y);
                }
            }
            if (POOL && wn == 0 && (lane & 3) == 0)
                atomicAdd(&g_pcnt[bgr], 1);
        }
    }
}

// ---------------- finalize: avg + classifier; self-cleans g_psum/g_pcnt --------
__global__ void pool_finalize_kernel(const float* __restrict__ wc, const float* __restrict__ bc,
                                     float* __restrict__ logits, float* __restrict__ avg_out) {
    int g = blockIdx.x;
    int lane = threadIdx.x;  // blockDim = 32
    float inv = 1.f / fmaxf((float)g_pcnt[g], 1.f);
    float4 v = *reinterpret_cast<const float4*>(g_psum + g * FC + lane * 4);
    *reinterpret_cast<float4*>(g_psum + g * FC + lane * 4) = make_float4(0.f, 0.f, 0.f, 0.f);
    if (lane == 0) g_pcnt[g] = 0;
    v.x *= inv; v.y *= inv; v.z *= inv; v.w *= inv;
    *reinterpret_cast<float4*>(avg_out + (size_t)g * FC + lane * 4) = v;
    int c = lane * 4;
    float s0 = v.x * wc[(c + 0) * NCLS + 0] + v.y * wc[(c + 1) * NCLS + 0] +
               v.z * wc[(c + 2) * NCLS + 0] + v.w * wc[(c + 3) * NCLS + 0];
    float s1 = v.x * wc[(c + 0) * NCLS + 1] + v.y * wc[(c + 1) * NCLS + 1] +
               v.z * wc[(c + 2) * NCLS + 1] + v.w * wc[(c + 3) * NCLS + 1];
#pragma unroll
    for (int o = 16; o > 0; o >>= 1) {
        s0 += __shfl_xor_sync(0xffffffffu, s0, o);
        s1 += __shfl_xor_sync(0xffffffffu, s1, o);
    }
    if (lane == 0) {
        logits[g * NCLS + 0] = s0 + bc[0];
        logits[g * NCLS + 1] = s1 + bc[1];
    }
}

// ---------------- launch ----------------
extern "C" void kernel_launch(void* const* d_in, const int* in_sizes, int n_in,
                              void* d_out, int out_size) {
    const float* x     = (const float*)d_in[0];
    const int*   ei    = (const int*)d_in[1];
    const int*   batch = (const int*)d_in[2];
    const float* w1l = (const float*)d_in[3];
    const float* w1r = (const float*)d_in[4];
    const float* b1  = (const float*)d_in[5];
    const float* g1  = (const float*)d_in[6];
    const float* be1 = (const float*)d_in[7];
    const float* w2l = (const float*)d_in[8];
    const float* w2r = (const float*)d_in[9];
    const float* b2  = (const float*)d_in[10];
    const float* g2  = (const float*)d_in[11];
    const float* be2 = (const float*)d_in[12];
    const float* w3l = (const float*)d_in[13];
    const float* w3r = (const float*)d_in[14];
    const float* b3  = (const float*)d_in[15];
    const float* g3  = (const float*)d_in[16];
    const float* be3 = (const float*)d_in[17];
    const float* wc  = (const float*)d_in[18];
    const float* bc  = (const float*)d_in[19];

    const int E = in_sizes[1] / 2;

    float* out    = (float*)d_out;
    float* logits = out;
    float* h3     = out + (size_t)N_GRAPHS * NCLS;
    float* avg    = h3 + (size_t)N_NODES * FC;

    float *p_h1 = nullptr, *p_h2 = nullptr;
    cudaGetSymbolAddress((void**)&p_h1, g_h1);
    cudaGetSymbolAddress((void**)&p_h2, g_h2);

    cudaFuncSetAttribute(sage_mma_kernel<false, false>,
                         cudaFuncAttributeMaxDynamicSharedMemorySize, SM_TOTAL);
    cudaFuncSetAttribute(sage_mma_kernel<true, false>,
                         cudaFuncAttributeMaxDynamicSharedMemorySize, SM_TOTAL);
    cudaFuncSetAttribute(sage_mma_kernel<true, true>,
                         cudaFuncAttributeMaxDynamicSharedMemorySize, SM_TOTAL);

    const int TC_BLKS = NBLK;  // 391
    const int NODE_WARP_BLKS = (int)(((size_t)N_NODES * 32 + 255) / 256);
    const int DP_THREADS = (E > 3 * 32768) ? E : 3 * 32768;
    const int EDGE_BLKS = (E + 255) / 256;

    // CSR build fused with weight prep (g_cnt is zero on entry; scan re-zeroes it)
    degree_prep_kernel<<<(DP_THREADS + 255) / 256, 256>>>(
        ei, E, w1l, w1r, w2l, w2r, w3l, w3r);
    scan_kernel<<<1, 1024>>>();
    csr_fill_kernel<<<EDGE_BLKS, 256>>>(ei, E);

    // layer 1
    gather_kernel<<<NODE_WARP_BLKS, 256>>>(x);
    sage_mma_kernel<false, false><<<TC_BLKS, 256, SM_TOTAL>>>(
        x, b1, g1, be1, p_h1, batch, 0);

    // layer 2 (residual)
    gather_kernel<<<NODE_WARP_BLKS, 256>>>(p_h1);
    sage_mma_kernel<true, false><<<TC_BLKS, 256, SM_TOTAL>>>(
        p_h1, b2, g2, be2, p_h2, batch, 1);

    // layer 3 (residual + pool) -> h3 straight into d_out
    gather_kernel<<<NODE_WARP_BLKS, 256>>>(p_h2);
    sage_mma_kernel<true, true><<<TC_BLKS, 256, SM_TOTAL>>>(
        p_h2, b3, g3, be3, h3, batch, 2);

    pool_finalize_kernel<<<N_GRAPHS, 32>>>(wc, bc, logits, avg);
}

// round 14
// speedup vs baseline: 1.1783x; 1.1223x over previous
#include <cuda_runtime.h>
#include <cuda_fp16.h>
#include <math.h>
#include <stdint.h>

#define N_NODES 50000
#define N_GRAPHS 512
#define FC 128
#define NCLS 2
#define EMAX 2000000
#define NBLK 391   // ceil(N_NODES/128)

// ---------------- scratch (device globals; no allocs allowed) ----------------
// Self-cleaning invariant: g_cnt, g_psum, g_pcnt are zero at entry of every
// kernel_launch call (zero-initialized at load; re-zeroed by their consumers).
__device__ float g_h1[(size_t)N_NODES * FC];
__device__ float g_h2[(size_t)N_NODES * FC];
// agg stored as pre-swizzled fp16 SMEM images: [NBLK][2 chunks][8192 half]
__device__ __half g_agb[(size_t)NBLK * 2 * 8192];
__device__ int   g_cnt[N_NODES];
__device__ int   g_off[N_NODES + 1];
__device__ int   g_cur[N_NODES];
__device__ int   g_csr[EMAX];
__device__ float g_psum[N_GRAPHS * FC];
__device__ int   g_pcnt[N_GRAPHS];
// pre-transposed fp16 hi/lo-split, pre-swizzled weights: [3 layers][4 chunks][8192]
__device__ __half g_bt_hi[3 * 4 * 8192];
__device__ __half g_bt_lo[3 * 4 * 8192];

#define SWZ128(b) ((b) ^ (((b) >> 3) & 0x70))

__device__ __forceinline__ uint32_t smem_to_u32(const void* p) {
    uint32_t a;
    asm("{ .reg .u64 t; cvta.to.shared.u64 t, %1; cvt.u32.u64 %0, t; }" : "=r"(a) : "l"(p));
    return a;
}
__device__ __forceinline__ void ldsm4(uint32_t& r0, uint32_t& r1, uint32_t& r2, uint32_t& r3,
                                      uint32_t addr) {
    asm volatile("ldmatrix.sync.aligned.m8n8.x4.shared.b16 {%0,%1,%2,%3}, [%4];"
                 : "=r"(r0), "=r"(r1), "=r"(r2), "=r"(r3) : "r"(addr));
}
__device__ __forceinline__ void mma16816(float* d, const uint32_t* a, uint32_t b0, uint32_t b1) {
    asm volatile(
        "mma.sync.aligned.m16n8k16.row.col.f32.f16.f16.f32 "
        "{%0,%1,%2,%3}, {%4,%5,%6,%7}, {%8,%9}, {%0,%1,%2,%3};"
        : "+f"(d[0]), "+f"(d[1]), "+f"(d[2]), "+f"(d[3])
        : "r"(a[0]), "r"(a[1]), "r"(a[2]), "r"(a[3]), "r"(b0), "r"(b1));
}

// ---------------- degree + weight prep (fused; prep covers first 98304 threads)
__global__ void degree_prep_kernel(
    const int* __restrict__ ei, int E,
    const float* __restrict__ w1l, const float* __restrict__ w1r,
    const float* __restrict__ w2l, const float* __restrict__ w2r,
    const float* __restrict__ w3l, const float* __restrict__ w3r)
{
    int i = blockIdx.x * blockDim.x + threadIdx.x;
    if (i < E) atomicAdd(&g_cnt[ei[E + i]], 1);
    if (i < 3 * 32768) {
        int layer = i >> 15;
        int li = i & 32767;
        int n = li >> 8, k = li & 255;
        const float* wl = (layer == 0) ? w1l : (layer == 1) ? w2l : w3l;
        const float* wr = (layer == 0) ? w1r : (layer == 1) ? w2r : w3r;
        float w = (k < 128) ? wl[k * FC + n] : wr[(k - 128) * FC + n];
        __half h = __float2half_rn(w);
        __half l = __float2half_rn(w - __half2float(h));
        int chunk = k >> 6, kk = k & 63;
        int swz = SWZ128(n * 128 + kk * 2);
        g_bt_hi[layer * 32768 + chunk * 8192 + (swz >> 1)] = h;
        g_bt_lo[layer * 32768 + chunk * 8192 + (swz >> 1)] = l;
    }
}

// ---------------- exclusive scan over g_cnt -> g_off/g_cur; re-zeroes g_cnt ----
__global__ void __launch_bounds__(1024) scan_kernel() {
    __shared__ int wsum[32];
    __shared__ int s_carry;
    const int tid = threadIdx.x, lane = tid & 31, wid = tid >> 5;
    if (tid == 0) s_carry = 0;
    __syncthreads();
    for (int base = 0; base < N_NODES; base += 4096) {
        int i0 = base + tid * 4;
        int4 c = make_int4(0, 0, 0, 0);
        if (i0 + 3 < N_NODES) c = *reinterpret_cast<int4*>(&g_cnt[i0]);
        int t1 = c.x + c.y;
        int t2 = t1 + c.z;
        int tot = t2 + c.w;
        int v = tot;
#pragma unroll
        for (int o = 1; o < 32; o <<= 1) {
            int t = __shfl_up_sync(0xffffffffu, v, o);
            if (lane >= o) v += t;
        }
        if (lane == 31) wsum[wid] = v;
        __syncthreads();
        if (wid == 0) {
            int s = wsum[lane];
            int so = s;
#pragma unroll
            for (int o = 1; o < 32; o <<= 1) {
                int t = __shfl_up_sync(0xffffffffu, s, o);
                if (lane >= o) s += t;
            }
            wsum[lane] = s - so;
        }
        __syncthreads();
        int incl = v + wsum[wid];
        int carry = s_carry;
        if (i0 + 3 < N_NODES) {
            int e0 = carry + incl - tot;
            int4 off = make_int4(e0, e0 + c.x, e0 + t1, e0 + t2);
            *reinterpret_cast<int4*>(&g_off[i0]) = off;
            *reinterpret_cast<int4*>(&g_cur[i0]) = off;
            *reinterpret_cast<int4*>(&g_cnt[i0]) = make_int4(0, 0, 0, 0);  // self-clean
        }
        __syncthreads();
        if (tid == 1023) s_carry = carry + incl;
        __syncthreads();
    }
    if (tid == 0) g_off[N_NODES] = s_carry;
}

__global__ void csr_fill_kernel(const int* __restrict__ ei, int E) {
    int e = blockIdx.x * blockDim.x + threadIdx.x;
    if (e >= E) return;
    int dst = __ldg(&ei[E + e]);
    int pos = atomicAdd(&g_cur[dst], 1);
    g_csr[pos] = __ldg(&ei[e]);
}

// ---------------- gather: mean over neighbors (warp/node); writes fp16
//                  pre-swizzled agg images directly -------------------------
__global__ void __launch_bounds__(256) gather_kernel(const float* __restrict__ x) {
    int w = (blockIdx.x * blockDim.x + threadIdx.x) >> 5;
    int lane = threadIdx.x & 31;
    if (w >= N_NODES) return;
    const int beg = g_off[w];
    const int end = g_off[w + 1];
    float4 a0 = make_float4(0.f, 0.f, 0.f, 0.f);
    float4 a1 = make_float4(0.f, 0.f, 0.f, 0.f);
    for (int base = beg; base < end; base += 32) {
        int idx = base + lane;
        int si = (idx < end) ? g_csr[idx] : 0;
        int m = end - base;
        if (m >= 32) {
#pragma unroll 4
            for (int j = 0; j < 32; j += 2) {
                int s0 = __shfl_sync(0xffffffffu, si, j);
                int s1 = __shfl_sync(0xffffffffu, si, j + 1);
                float4 v0 = __ldg(reinterpret_cast<const float4*>(x + (size_t)s0 * FC) + lane);
                float4 v1 = __ldg(reinterpret_cast<const float4*>(x + (size_t)s1 * FC) + lane);
                a0.x += v0.x; a0.y += v0.y; a0.z += v0.z; a0.w += v0.w;
                a1.x += v1.x; a1.y += v1.y; a1.z += v1.z; a1.w += v1.w;
            }
        } else {
            int j = 0;
            for (; j + 1 < m; j += 2) {
                int s0 = __shfl_sync(0xffffffffu, si, j);
                int s1 = __shfl_sync(0xffffffffu, si, j + 1);
                float4 v0 = __ldg(reinterpret_cast<const float4*>(x + (size_t)s0 * FC) + lane);
                float4 v1 = __ldg(reinterpret_cast<const float4*>(x + (size_t)s1 * FC) + lane);
                a0.x += v0.x; a0.y += v0.y; a0.z += v0.z; a0.w += v0.w;
                a1.x += v1.x; a1.y += v1.y; a1.z += v1.z; a1.w += v1.w;
            }
            if (j < m) {
                int s0 = __shfl_sync(0xffffffffu, si, j);
                float4 v0 = __ldg(reinterpret_cast<const float4*>(x + (size_t)s0 * FC) + lane);
                a0.x += v0.x; a0.y += v0.y; a0.z += v0.z; a0.w += v0.w;
            }
        }
    }
    float inv = 1.f / fmaxf((float)(end - beg), 1.f);
    float v0 = (a0.x + a1.x) * inv;
    float v1 = (a0.y + a1.y) * inv;
    float v2 = (a0.z + a1.z) * inv;
    float v3 = (a0.w + a1.w) * inv;
    __half2 hh[2] = {__floats2half2_rn(v0, v1), __floats2half2_rn(v2, v3)};
    int blk = w >> 7, r = w & 127;
    int c = lane >> 4;              // chunk (cols 0-63 / 64-127)
    int kk = (lane & 15) * 4;       // col within chunk
    int swz = SWZ128(r * 128 + kk * 2);
    size_t img = ((size_t)blk * 2 + c) * 16384;  // bytes
    *reinterpret_cast<uint2*>(reinterpret_cast<char*>(g_agb) + img + swz) =
        *reinterpret_cast<uint2*>(hh);
}

// ---------------- tensor-core fused layer (mma.sync fp16, B split hi/lo) ------
// D = A_fp16 · (B_hi + B_lo)  — B split is exact; only A is quantized (2^-11).
#define SM_A   0
#define SM_BH  16384
#define SM_BL  32768
#define SM_PS  49152
#define SM_PQ  (SM_PS + 1024)
#define SM_TOTAL (SM_PQ + 1024)

template <bool RESID, bool POOL>
__global__ void __launch_bounds__(256) sage_mma_kernel(
    const float* __restrict__ xin,
    const float* __restrict__ bias, const float* __restrict__ gam,
    const float* __restrict__ bet,
    float* __restrict__ hout,
    const int* __restrict__ batch,
    int layer)
{
    extern __shared__ char smem[];
    const uint32_t sb = smem_to_u32(smem);
    const int tid = threadIdx.x;
    const int lane = tid & 31;
    const int wid = tid >> 5;
    const int wm = wid & 3;
    const int wn = wid >> 2;
    const int row0 = blockIdx.x * 128;

    float d[2][8][4];
#pragma unroll
    for (int i = 0; i < 2; i++)
#pragma unroll
        for (int j = 0; j < 8; j++)
#pragma unroll
            for (int t = 0; t < 4; t++) d[i][j][t] = 0.f;

    const int lm = lane >> 3, lr = lane & 7;
    int a_rowb[2];
#pragma unroll
    for (int mi = 0; mi < 2; mi++)
        a_rowb[mi] = (wm * 32 + mi * 16 + (lm & 1) * 8 + lr) * 128 + (lm >> 1) * 16;
    int b_rowb[4];
#pragma unroll
    for (int np = 0; np < 4; np++)
        b_rowb[np] = (wn * 64 + np * 16 + (lm >> 1) * 8 + lr) * 128 + (lm & 1) * 16;

    const __half* btH = g_bt_hi + layer * 32768;
    const __half* btL = g_bt_lo + layer * 32768;

    for (int chunk = 0; chunk < 4; chunk++) {
        if (chunk < 2) {
            // ---- agg chunk: straight copy of pre-swizzled fp16 image ----
            const uint4* ag = reinterpret_cast<const uint4*>(
                g_agb + ((size_t)blockIdx.x * 2 + chunk) * 8192);
            uint4* da = reinterpret_cast<uint4*>(smem + SM_A);
#pragma unroll
            for (int it = 0; it < 4; it++) {
                int i = it * 256 + tid;
                da[i] = __ldg(ag + i);
            }
        } else {
            // ---- xin chunk: load fp32, convert to fp16, swizzle ----
            const int kofs = (chunk & 1) * 64;
#pragma unroll
            for (int it = 0; it < 4; it++) {
                int idx = it * 256 + tid;       // 0..1023
                int r = idx >> 3;
                int kk0 = (idx & 7) * 8;
                int gr = row0 + r;
                float4 fa = make_float4(0.f, 0.f, 0.f, 0.f), fb = fa;
                if (gr < N_NODES) {
                    const float4* p = reinterpret_cast<const float4*>(
                        xin + (size_t)gr * FC + kofs + kk0);
                    fa = p[0]; fb = p[1];
                }
                __half2 hh[4];
                hh[0] = __floats2half2_rn(fa.x, fa.y);
                hh[1] = __floats2half2_rn(fa.z, fa.w);
                hh[2] = __floats2half2_rn(fb.x, fb.y);
                hh[3] = __floats2half2_rn(fb.z, fb.w);
                int swz = SWZ128(r * 128 + kk0 * 2);
                *reinterpret_cast<uint4*>(smem + SM_A + swz) = *reinterpret_cast<uint4*>(hh);
            }
        }
        // ---- copy pre-swizzled B chunk (hi + lo) ----
        {
            const uint4* bh = reinterpret_cast<const uint4*>(btH + chunk * 8192);
            const uint4* bl = reinterpret_cast<const uint4*>(btL + chunk * 8192);
            uint4* dh = reinterpret_cast<uint4*>(smem + SM_BH);
            uint4* dl = reinterpret_cast<uint4*>(smem + SM_BL);
#pragma unroll
            for (int it = 0; it < 4; it++) {
                int i = it * 256 + tid;
                dh[i] = __ldg(bh + i);
                dl[i] = __ldg(bl + i);
            }
        }
        __syncthreads();

#pragma unroll
        for (int ks = 0; ks < 4; ks++) {
            uint32_t ar[2][4];
#pragma unroll
            for (int mi = 0; mi < 2; mi++) {
                uint32_t off = SWZ128(a_rowb[mi] + ks * 32);
                ldsm4(ar[mi][0], ar[mi][1], ar[mi][2], ar[mi][3], sb + SM_A + off);
            }
#pragma unroll
            for (int np = 0; np < 4; np++) {
                uint32_t off = SWZ128(b_rowb[np] + ks * 32);
                uint32_t bh0, bh1, bh2, bh3, bl0, bl1, bl2, bl3;
                ldsm4(bh0, bh1, bh2, bh3, sb + SM_BH + off);
                ldsm4(bl0, bl1, bl2, bl3, sb + SM_BL + off);
#pragma unroll
                for (int mi = 0; mi < 2; mi++) {
                    mma16816(d[mi][np * 2 + 0], ar[mi], bh0, bh1);
                    mma16816(d[mi][np * 2 + 0], ar[mi], bl0, bl1);
                    mma16816(d[mi][np * 2 + 1], ar[mi], bh2, bh3);
                    mma16816(d[mi][np * 2 + 1], ar[mi], bl2, bl3);
                }
            }
        }
        __syncthreads();
    }

    // ---------- epilogue: bias, relu, residual, LayerNorm (+ pool) ----------
    const int cb = wn * 64 + (lane & 3) * 2;
    float2 bb[8];
#pragma unroll
    for (int ni = 0; ni < 8; ni++)
        bb[ni] = __ldg(reinterpret_cast<const float2*>(bias + cb + ni * 8));

    float s[2][2] = {{0.f, 0.f}, {0.f, 0.f}};
    float q[2][2] = {{0.f, 0.f}, {0.f, 0.f}};
#pragma unroll
    for (int mi = 0; mi < 2; mi++) {
#pragma unroll
        for (int z = 0; z < 2; z++) {
            int rl = wm * 32 + mi * 16 + z * 8 + (lane >> 2);
            int gr = row0 + rl;
            bool valid = gr < N_NODES;
#pragma unroll
            for (int ni = 0; ni < 8; ni++) {
                float2 rv = make_float2(0.f, 0.f);
                if (RESID && valid)
                    rv = *reinterpret_cast<const float2*>(xin + (size_t)gr * FC + cb + ni * 8);
                float v0 = fmaxf(d[mi][ni][z * 2 + 0] + bb[ni].x, 0.f) + rv.x;
                float v1 = fmaxf(d[mi][ni][z * 2 + 1] + bb[ni].y, 0.f) + rv.y;
                s[mi][z] += v0 + v1;
                q[mi][z] += v0 * v0 + v1 * v1;
                d[mi][ni][z * 2 + 0] = v0;
                d[mi][ni][z * 2 + 1] = v1;
            }
        }
    }
    float* ps = reinterpret_cast<float*>(smem + SM_PS);
    float* pq = reinterpret_cast<float*>(smem + SM_PQ);
#pragma unroll
    for (int mi = 0; mi < 2; mi++) {
#pragma unroll
        for (int z = 0; z < 2; z++) {
            float ss = s[mi][z], qq = q[mi][z];
            ss += __shfl_xor_sync(0xffffffffu, ss, 1);
            ss += __shfl_xor_sync(0xffffffffu, ss, 2);
            qq += __shfl_xor_sync(0xffffffffu, qq, 1);
            qq += __shfl_xor_sync(0xffffffffu, qq, 2);
            if ((lane & 3) == 0) {
                int rl = wm * 32 + mi * 16 + z * 8 + (lane >> 2);
                ps[wn * 128 + rl] = ss;
                pq[wn * 128 + rl] = qq;
            }
        }
    }
    __syncthreads();
#pragma unroll
    for (int mi = 0; mi < 2; mi++) {
#pragma unroll
        for (int z = 0; z < 2; z++) {
            int rl = wm * 32 + mi * 16 + z * 8 + (lane >> 2);
            int gr = row0 + rl;
            if (gr >= N_NODES) continue;
            float S = ps[rl] + ps[128 + rl];
            float Q = pq[rl] + pq[128 + rl];
            float mean = S * (1.f / 128.f);
            float var = Q * (1.f / 128.f) - mean * mean;
            float rs = rsqrtf(var + 1e-5f);
            int bgr = POOL ? __ldg(&batch[gr]) : 0;
#pragma unroll
            for (int ni = 0; ni < 8; ni++) {
                float2 g2 = __ldg(reinterpret_cast<const float2*>(gam + cb + ni * 8));
                float2 e2 = __ldg(reinterpret_cast<const float2*>(bet + cb + ni * 8));
                float2 o2;
                o2.x = (d[mi][ni][z * 2 + 0] - mean) * rs * g2.x + e2.x;
                o2.y = (d[mi][ni][z * 2 + 1] - mean) * rs * g2.y + e2.y;
                *reinterpret_cast<float2*>(hout + (size_t)gr * FC + cb + ni * 8) = o2;
                if (POOL) {
                    atomicAdd(&g_psum[bgr * FC + cb + ni * 8], o2.x);
                    atomicAdd(&g_psum[bgr * FC + cb + ni * 8 + 1], o2.y);
                }
            }
            if (POOL && wn == 0 && (lane & 3) == 0)
                atomicAdd(&g_pcnt[bgr], 1);
        }
    }
}

// ---------------- finalize: avg + classifier; self-cleans g_psum/g_pcnt --------
__global__ void pool_finalize_kernel(const float* __restrict__ wc, const float* __restrict__ bc,
                                     float* __restrict__ logits, float* __restrict__ avg_out) {
    int g = blockIdx.x;
    int lane = threadIdx.x;  // blockDim = 32
    float inv = 1.f / fmaxf((float)g_pcnt[g], 1.f);
    float4 v = *reinterpret_cast<const float4*>(g_psum + g * FC + lane * 4);
    *reinterpret_cast<float4*>(g_psum + g * FC + lane * 4) = make_float4(0.f, 0.f, 0.f, 0.f);
    if (lane == 0) g_pcnt[g] = 0;
    v.x *= inv; v.y *= inv; v.z *= inv; v.w *= inv;
    *reinterpret_cast<float4*>(avg_out + (size_t)g * FC + lane * 4) = v;
    int c = lane * 4;
    float s0 = v.x * wc[(c + 0) * NCLS + 0] + v.y * wc[(c + 1) * NCLS + 0] +
               v.z * wc[(c + 2) * NCLS + 0] + v.w * wc[(c + 3) * NCLS + 0];
    float s1 = v.x * wc[(c + 0) * NCLS + 1] + v.y * wc[(c + 1) * NCLS + 1] +
               v.z * wc[(c + 2) * NCLS + 1] + v.w * wc[(c + 3) * NCLS + 1];
#pragma unroll
    for (int o = 16; o > 0; o >>= 1) {
        s0 += __shfl_xor_sync(0xffffffffu, s0, o);
        s1 += __shfl_xor_sync(0xffffffffu, s1, o);
    }
    if (lane == 0) {
        logits[g * NCLS + 0] = s0 + bc[0];
        logits[g * NCLS + 1] = s1 + bc[1];
    }
}

// ---------------- launch ----------------
extern "C" void kernel_launch(void* const* d_in, const int* in_sizes, int n_in,
                              void* d_out, int out_size) {
    const float* x     = (const float*)d_in[0];
    const int*   ei    = (const int*)d_in[1];
    const int*   batch = (const int*)d_in[2];
    const float* w1l = (const float*)d_in[3];
    const float* w1r = (const float*)d_in[4];
    const float* b1  = (const float*)d_in[5];
    const float* g1  = (const float*)d_in[6];
    const float* be1 = (const float*)d_in[7];
    const float* w2l = (const float*)d_in[8];
    const float* w2r = (const float*)d_in[9];
    const float* b2  = (const float*)d_in[10];
    const float* g2  = (const float*)d_in[11];
    const float* be2 = (const float*)d_in[12];
    const float* w3l = (const float*)d_in[13];
    const float* w3r = (const float*)d_in[14];
    const float* b3  = (const float*)d_in[15];
    const float* g3  = (const float*)d_in[16];
    const float* be3 = (const float*)d_in[17];
    const float* wc  = (const float*)d_in[18];
    const float* bc  = (const float*)d_in[19];

    const int E = in_sizes[1] / 2;

    float* out    = (float*)d_out;
    float* logits = out;
    float* h3     = out + (size_t)N_GRAPHS * NCLS;
    float* avg    = h3 + (size_t)N_NODES * FC;

    float *p_h1 = nullptr, *p_h2 = nullptr;
    cudaGetSymbolAddress((void**)&p_h1, g_h1);
    cudaGetSymbolAddress((void**)&p_h2, g_h2);

    cudaFuncSetAttribute(sage_mma_kernel<false, false>,
                         cudaFuncAttributeMaxDynamicSharedMemorySize, SM_TOTAL);
    cudaFuncSetAttribute(sage_mma_kernel<true, false>,
                         cudaFuncAttributeMaxDynamicSharedMemorySize, SM_TOTAL);
    cudaFuncSetAttribute(sage_mma_kernel<true, true>,
                         cudaFuncAttributeMaxDynamicSharedMemorySize, SM_TOTAL);

    const int TC_BLKS = NBLK;  // 391
    const int NODE_WARP_BLKS = (int)(((size_t)N_NODES * 32 + 255) / 256);
    const int DP_THREADS = (E > 3 * 32768) ? E : 3 * 32768;
    const int EDGE_BLKS = (E + 255) / 256;

    // CSR build fused with weight prep (g_cnt is zero on entry; scan re-zeroes it)
    degree_prep_kernel<<<(DP_THREADS + 255) / 256, 256>>>(
        ei, E, w1l, w1r, w2l, w2r, w3l, w3r);
    scan_kernel<<<1, 1024>>>();
    csr_fill_kernel<<<EDGE_BLKS, 256>>>(ei, E);

    // layer 1
    gather_kernel<<<NODE_WARP_BLKS, 256>>>(x);
    sage_mma_kernel<false, false><<<TC_BLKS, 256, SM_TOTAL>>>(
        x, b1, g1, be1, p_h1, batch, 0);

    // layer 2 (residual)
    gather_kernel<<<NODE_WARP_BLKS, 256>>>(p_h1);
    sage_mma_kernel<true, false><<<TC_BLKS, 256, SM_TOTAL>>>(
        p_h1, b2, g2, be2, p_h2, batch, 1);

    // layer 3 (residual + pool) -> h3 straight into d_out
    gather_kernel<<<NODE_WARP_BLKS, 256>>>(p_h2);
    sage_mma_kernel<true, true><<<TC_BLKS, 256, SM_TOTAL>>>(
        p_h2, b3, g3, be3, h3, batch, 2);

    pool_finalize_kernel<<<N_GRAPHS, 32>>>(wc, bc, logits, avg);
}

// round 15
// speedup vs baseline: 1.3605x; 1.1546x over previous
#include <cuda_runtime.h>
#include <cuda_fp16.h>
#include <math.h>
#include <stdint.h>

#define N_NODES 50000
#define N_GRAPHS 512
#define FC 128
#define NCLS 2
#define EMAX 2000000
#define NBLK 391   // ceil(N_NODES/128)

// ---------------- scratch (device globals; no allocs allowed) ----------------
// Self-cleaning invariant: g_cnt, g_psum, g_pcnt are zero at entry of every
// kernel_launch call (zero-initialized at load; re-zeroed by their consumers).
__device__ float g_h1[(size_t)N_NODES * FC];
__device__ float g_h2[(size_t)N_NODES * FC];
// agg stored as pre-swizzled fp16 SMEM images: [NBLK][2 chunks][8192 half]
__device__ __half g_agb[(size_t)NBLK * 2 * 8192];
__device__ int   g_cnt[N_NODES];
__device__ int   g_off[N_NODES + 1];
__device__ int   g_cur[N_NODES];
__device__ int   g_csr[EMAX];
__device__ float g_psum[N_GRAPHS * FC];
__device__ int   g_pcnt[N_GRAPHS];
// pre-transposed fp16, pre-swizzled weights: [3 layers][4 chunks][8192]
__device__ __half g_bt[3 * 4 * 8192];

#define SWZ128(b) ((b) ^ (((b) >> 3) & 0x70))

__device__ __forceinline__ uint32_t smem_to_u32(const void* p) {
    uint32_t a;
    asm("{ .reg .u64 t; cvta.to.shared.u64 t, %1; cvt.u32.u64 %0, t; }" : "=r"(a) : "l"(p));
    return a;
}
__device__ __forceinline__ void ldsm4(uint32_t& r0, uint32_t& r1, uint32_t& r2, uint32_t& r3,
                                      uint32_t addr) {
    asm volatile("ldmatrix.sync.aligned.m8n8.x4.shared.b16 {%0,%1,%2,%3}, [%4];"
                 : "=r"(r0), "=r"(r1), "=r"(r2), "=r"(r3) : "r"(addr));
}
__device__ __forceinline__ void mma16816(float* d, const uint32_t* a, uint32_t b0, uint32_t b1) {
    asm volatile(
        "mma.sync.aligned.m16n8k16.row.col.f32.f16.f16.f32 "
        "{%0,%1,%2,%3}, {%4,%5,%6,%7}, {%8,%9}, {%0,%1,%2,%3};"
        : "+f"(d[0]), "+f"(d[1]), "+f"(d[2]), "+f"(d[3])
        : "r"(a[0]), "r"(a[1]), "r"(a[2]), "r"(a[3]), "r"(b0), "r"(b1));
}

// ---------------- degree + weight prep (fused; prep covers first 98304 threads)
__global__ void degree_prep_kernel(
    const int* __restrict__ ei, int E,
    const float* __restrict__ w1l, const float* __restrict__ w1r,
    const float* __restrict__ w2l, const float* __restrict__ w2r,
    const float* __restrict__ w3l, const float* __restrict__ w3r)
{
    int i = blockIdx.x * blockDim.x + threadIdx.x;
    if (i < E) atomicAdd(&g_cnt[ei[E + i]], 1);
    if (i < 3 * 32768) {
        int layer = i >> 15;
        int li = i & 32767;
        int n = li >> 8, k = li & 255;
        const float* wl = (layer == 0) ? w1l : (layer == 1) ? w2l : w3l;
        const float* wr = (layer == 0) ? w1r : (layer == 1) ? w2r : w3r;
        float w = (k < 128) ? wl[k * FC + n] : wr[(k - 128) * FC + n];
        int chunk = k >> 6, kk = k & 63;
        int swz = SWZ128(n * 128 + kk * 2);
        g_bt[layer * 32768 + chunk * 8192 + (swz >> 1)] = __float2half_rn(w);
    }
}

// ---------------- exclusive scan over g_cnt -> g_off/g_cur; re-zeroes g_cnt ----
__global__ void __launch_bounds__(1024) scan_kernel() {
    __shared__ int wsum[32];
    __shared__ int s_carry;
    const int tid = threadIdx.x, lane = tid & 31, wid = tid >> 5;
    if (tid == 0) s_carry = 0;
    __syncthreads();
    for (int base = 0; base < N_NODES; base += 4096) {
        int i0 = base + tid * 4;
        int4 c = make_int4(0, 0, 0, 0);
        if (i0 + 3 < N_NODES) c = *reinterpret_cast<int4*>(&g_cnt[i0]);
        int t1 = c.x + c.y;
        int t2 = t1 + c.z;
        int tot = t2 + c.w;
        int v = tot;
#pragma unroll
        for (int o = 1; o < 32; o <<= 1) {
            int t = __shfl_up_sync(0xffffffffu, v, o);
            if (lane >= o) v += t;
        }
        if (lane == 31) wsum[wid] = v;
        __syncthreads();
        if (wid == 0) {
            int s = wsum[lane];
            int so = s;
#pragma unroll
            for (int o = 1; o < 32; o <<= 1) {
                int t = __shfl_up_sync(0xffffffffu, s, o);
                if (lane >= o) s += t;
            }
            wsum[lane] = s - so;
        }
        __syncthreads();
        int incl = v + wsum[wid];
        int carry = s_carry;
        if (i0 + 3 < N_NODES) {
            int e0 = carry + incl - tot;
            int4 off = make_int4(e0, e0 + c.x, e0 + t1, e0 + t2);
            *reinterpret_cast<int4*>(&g_off[i0]) = off;
            *reinterpret_cast<int4*>(&g_cur[i0]) = off;
            *reinterpret_cast<int4*>(&g_cnt[i0]) = make_int4(0, 0, 0, 0);  // self-clean
        }
        __syncthreads();
        if (tid == 1023) s_carry = carry + incl;
        __syncthreads();
    }
    if (tid == 0) g_off[N_NODES] = s_carry;
}

__global__ void csr_fill_kernel(const int* __restrict__ ei, int E) {
    int e = blockIdx.x * blockDim.x + threadIdx.x;
    if (e >= E) return;
    int dst = __ldg(&ei[E + e]);
    int pos = atomicAdd(&g_cur[dst], 1);
    g_csr[pos] = __ldg(&ei[e]);
}

// ---------------- gather: mean over neighbors (warp/node); writes fp16
//                  pre-swizzled agg images directly -------------------------
__global__ void __launch_bounds__(256) gather_kernel(const float* __restrict__ x) {
    int w = (blockIdx.x * blockDim.x + threadIdx.x) >> 5;
    int lane = threadIdx.x & 31;
    if (w >= N_NODES) return;
    const int beg = g_off[w];
    const int end = g_off[w + 1];
    float4 a0 = make_float4(0.f, 0.f, 0.f, 0.f);
    float4 a1 = make_float4(0.f, 0.f, 0.f, 0.f);
    for (int base = beg; base < end; base += 32) {
        int idx = base + lane;
        int si = (idx < end) ? g_csr[idx] : 0;
        int m = end - base;
        if (m >= 32) {
#pragma unroll 4
            for (int j = 0; j < 32; j += 2) {
                int s0 = __shfl_sync(0xffffffffu, si, j);
                int s1 = __shfl_sync(0xffffffffu, si, j + 1);
                float4 v0 = __ldg(reinterpret_cast<const float4*>(x + (size_t)s0 * FC) + lane);
                float4 v1 = __ldg(reinterpret_cast<const float4*>(x + (size_t)s1 * FC) + lane);
                a0.x += v0.x; a0.y += v0.y; a0.z += v0.z; a0.w += v0.w;
                a1.x += v1.x; a1.y += v1.y; a1.z += v1.z; a1.w += v1.w;
            }
        } else {
            int j = 0;
            for (; j + 1 < m; j += 2) {
                int s0 = __shfl_sync(0xffffffffu, si, j);
                int s1 = __shfl_sync(0xffffffffu, si, j + 1);
                float4 v0 = __ldg(reinterpret_cast<const float4*>(x + (size_t)s0 * FC) + lane);
                float4 v1 = __ldg(reinterpret_cast<const float4*>(x + (size_t)s1 * FC) + lane);
                a0.x += v0.x; a0.y += v0.y; a0.z += v0.z; a0.w += v0.w;
                a1.x += v1.x; a1.y += v1.y; a1.z += v1.z; a1.w += v1.w;
            }
            if (j < m) {
                int s0 = __shfl_sync(0xffffffffu, si, j);
                float4 v0 = __ldg(reinterpret_cast<const float4*>(x + (size_t)s0 * FC) + lane);
                a0.x += v0.x; a0.y += v0.y; a0.z += v0.z; a0.w += v0.w;
            }
        }
    }
    float inv = 1.f / fmaxf((float)(end - beg), 1.f);
    float v0 = (a0.x + a1.x) * inv;
    float v1 = (a0.y + a1.y) * inv;
    float v2 = (a0.z + a1.z) * inv;
    float v3 = (a0.w + a1.w) * inv;
    __half2 hh[2] = {__floats2half2_rn(v0, v1), __floats2half2_rn(v2, v3)};
    int blk = w >> 7, r = w & 127;
    int c = lane >> 4;              // chunk (cols 0-63 / 64-127)
    int kk = (lane & 15) * 4;       // col within chunk
    int swz = SWZ128(r * 128 + kk * 2);
    size_t img = ((size_t)blk * 2 + c) * 16384;  // bytes
    *reinterpret_cast<uint2*>(reinterpret_cast<char*>(g_agb) + img + swz) =
        *reinterpret_cast<uint2*>(hh);
}

// ---------------- tensor-core fused layer (single-pass fp16 mma.sync) ---------
#define SM_A   0
#define SM_B   16384
#define SM_PS  32768
#define SM_PQ  (SM_PS + 1024)
#define SM_TOTAL (SM_PQ + 1024)

template <bool RESID, bool POOL>
__global__ void __launch_bounds__(256) sage_mma_kernel(
    const float* __restrict__ xin,
    const float* __restrict__ bias, const float* __restrict__ gam,
    const float* __restrict__ bet,
    float* __restrict__ hout,
    const int* __restrict__ batch,
    int layer)
{
    extern __shared__ char smem[];
    const uint32_t sb = smem_to_u32(smem);
    const int tid = threadIdx.x;
    const int lane = tid & 31;
    const int wid = tid >> 5;
    const int wm = wid & 3;
    const int wn = wid >> 2;
    const int row0 = blockIdx.x * 128;

    float d[2][8][4];
#pragma unroll
    for (int i = 0; i < 2; i++)
#pragma unroll
        for (int j = 0; j < 8; j++)
#pragma unroll
            for (int t = 0; t < 4; t++) d[i][j][t] = 0.f;

    const int lm = lane >> 3, lr = lane & 7;
    int a_rowb[2];
#pragma unroll
    for (int mi = 0; mi < 2; mi++)
        a_rowb[mi] = (wm * 32 + mi * 16 + (lm & 1) * 8 + lr) * 128 + (lm >> 1) * 16;
    int b_rowb[4];
#pragma unroll
    for (int np = 0; np < 4; np++)
        b_rowb[np] = (wn * 64 + np * 16 + (lm >> 1) * 8 + lr) * 128 + (lm & 1) * 16;

    const __half* bt = g_bt + layer * 32768;

    for (int chunk = 0; chunk < 4; chunk++) {
        if (chunk < 2) {
            // ---- agg chunk: straight copy of pre-swizzled fp16 image ----
            const uint4* ag = reinterpret_cast<const uint4*>(
                g_agb + ((size_t)blockIdx.x * 2 + chunk) * 8192);
            uint4* da = reinterpret_cast<uint4*>(smem + SM_A);
#pragma unroll
            for (int it = 0; it < 4; it++) {
                int i = it * 256 + tid;
                da[i] = __ldg(ag + i);
            }
        } else {
            // ---- xin chunk: load fp32, convert to fp16, swizzle ----
            const int kofs = (chunk & 1) * 64;
#pragma unroll
            for (int it = 0; it < 4; it++) {
                int idx = it * 256 + tid;       // 0..1023
                int r = idx >> 3;
                int kk0 = (idx & 7) * 8;
                int gr = row0 + r;
                float4 fa = make_float4(0.f, 0.f, 0.f, 0.f), fb = fa;
                if (gr < N_NODES) {
                    const float4* p = reinterpret_cast<const float4*>(
                        xin + (size_t)gr * FC + kofs + kk0);
                    fa = p[0]; fb = p[1];
                }
                __half2 hh[4];
                hh[0] = __floats2half2_rn(fa.x, fa.y);
                hh[1] = __floats2half2_rn(fa.z, fa.w);
                hh[2] = __floats2half2_rn(fb.x, fb.y);
                hh[3] = __floats2half2_rn(fb.z, fb.w);
                int swz = SWZ128(r * 128 + kk0 * 2);
                *reinterpret_cast<uint4*>(smem + SM_A + swz) = *reinterpret_cast<uint4*>(hh);
            }
        }
        // ---- copy pre-swizzled B chunk ----
        {
            const uint4* bsrc = reinterpret_cast<const uint4*>(bt + chunk * 8192);
            uint4* db = reinterpret_cast<uint4*>(smem + SM_B);
#pragma unroll
            for (int it = 0; it < 4; it++) {
                int i = it * 256 + tid;
                db[i] = __ldg(bsrc + i);
            }
        }
        __syncthreads();

#pragma unroll
        for (int ks = 0; ks < 4; ks++) {
            uint32_t ar[2][4];
#pragma unroll
            for (int mi = 0; mi < 2; mi++) {
                uint32_t off = SWZ128(a_rowb[mi] + ks * 32);
                ldsm4(ar[mi][0], ar[mi][1], ar[mi][2], ar[mi][3], sb + SM_A + off);
            }
#pragma unroll
            for (int np = 0; np < 4; np++) {
                uint32_t off = SWZ128(b_rowb[np] + ks * 32);
                uint32_t b0, b1, b2, b3;
                ldsm4(b0, b1, b2, b3, sb + SM_B + off);
#pragma unroll
                for (int mi = 0; mi < 2; mi++) {
                    mma16816(d[mi][np * 2 + 0], ar[mi], b0, b1);
                    mma16816(d[mi][np * 2 + 1], ar[mi], b2, b3);
                }
            }
        }
        __syncthreads();
    }

    // ---------- epilogue: bias, relu, residual, LayerNorm (+ pool) ----------
    const int cb = wn * 64 + (lane & 3) * 2;
    float2 bb[8];
#pragma unroll
    for (int ni = 0; ni < 8; ni++)
        bb[ni] = __ldg(reinterpret_cast<const float2*>(bias + cb + ni * 8));

    float s[2][2] = {{0.f, 0.f}, {0.f, 0.f}};
    float q[2][2] = {{0.f, 0.f}, {0.f, 0.f}};
#pragma unroll
    for (int mi = 0; mi < 2; mi++) {
#pragma unroll
        for (int z = 0; z < 2; z++) {
            int rl = wm * 32 + mi * 16 + z * 8 + (lane >> 2);
            int gr = row0 + rl;
            bool valid = gr < N_NODES;
#pragma unroll
            for (int ni = 0; ni < 8; ni++) {
                float2 rv = make_float2(0.f, 0.f);
                if (RESID && valid)
                    rv = *reinterpret_cast<const float2*>(xin + (size_t)gr * FC + cb + ni * 8);
                float v0 = fmaxf(d[mi][ni][z * 2 + 0] + bb[ni].x, 0.f) + rv.x;
                float v1 = fmaxf(d[mi][ni][z * 2 + 1] + bb[ni].y, 0.f) + rv.y;
                s[mi][z] += v0 + v1;
                q[mi][z] += v0 * v0 + v1 * v1;
                d[mi][ni][z * 2 + 0] = v0;
                d[mi][ni][z * 2 + 1] = v1;
            }
        }
    }
    float* ps = reinterpret_cast<float*>(smem + SM_PS);
    float* pq = reinterpret_cast<float*>(smem + SM_PQ);
#pragma unroll
    for (int mi = 0; mi < 2; mi++) {
#pragma unroll
        for (int z = 0; z < 2; z++) {
            float ss = s[mi][z], qq = q[mi][z];
            ss += __shfl_xor_sync(0xffffffffu, ss, 1);
            ss += __shfl_xor_sync(0xffffffffu, ss, 2);
            qq += __shfl_xor_sync(0xffffffffu, qq, 1);
            qq += __shfl_xor_sync(0xffffffffu, qq, 2);
            if ((lane & 3) == 0) {
                int rl = wm * 32 + mi * 16 + z * 8 + (lane >> 2);
                ps[wn * 128 + rl] = ss;
                pq[wn * 128 + rl] = qq;
            }
        }
    }
    __syncthreads();
#pragma unroll
    for (int mi = 0; mi < 2; mi++) {
#pragma unroll
        for (int z = 0; z < 2; z++) {
            int rl = wm * 32 + mi * 16 + z * 8 + (lane >> 2);
            int gr = row0 + rl;
            if (gr >= N_NODES) continue;
            float S = ps[rl] + ps[128 + rl];
            float Q = pq[rl] + pq[128 + rl];
            float mean = S * (1.f / 128.f);
            float var = Q * (1.f / 128.f) - mean * mean;
            float rs = rsqrtf(var + 1e-5f);
            int bgr = POOL ? __ldg(&batch[gr]) : 0;
#pragma unroll
            for (int ni = 0; ni < 8; ni++) {
                float2 g2 = __ldg(reinterpret_cast<const float2*>(gam + cb + ni * 8));
                float2 e2 = __ldg(reinterpret_cast<const float2*>(bet + cb + ni * 8));
                float2 o2;
                o2.x = (d[mi][ni][z * 2 + 0] - mean) * rs * g2.x + e2.x;
                o2.y = (d[mi][ni][z * 2 + 1] - mean) * rs * g2.y + e2.y;
                *reinterpret_cast<float2*>(hout + (size_t)gr * FC + cb + ni * 8) = o2;
                if (POOL) {
                    atomicAdd(&g_psum[bgr * FC + cb + ni * 8], o2.x);
                    atomicAdd(&g_psum[bgr * FC + cb + ni * 8 + 1], o2.y);
                }
            }
            if (POOL && wn == 0 && (lane & 3) == 0)
                atomicAdd(&g_pcnt[bgr], 1);
        }
    }
}

// ---------------- finalize: avg + classifier; self-cleans g_psum/g_pcnt --------
__global__ void pool_finalize_kernel(const float* __restrict__ wc, const float* __restrict__ bc,
                                     float* __restrict__ logits, float* __restrict__ avg_out) {
    int g = blockIdx.x;
    int lane = threadIdx.x;  // blockDim = 32
    float inv = 1.f / fmaxf((float)g_pcnt[g], 1.f);
    float4 v = *reinterpret_cast<const float4*>(g_psum + g * FC + lane * 4);
    *reinterpret_cast<float4*>(g_psum + g * FC + lane * 4) = make_float4(0.f, 0.f, 0.f, 0.f);
    if (lane == 0) g_pcnt[g] = 0;
    v.x *= inv; v.y *= inv; v.z *= inv; v.w *= inv;
    *reinterpret_cast<float4*>(avg_out + (size_t)g * FC + lane * 4) = v;
    int c = lane * 4;
    float s0 = v.x * wc[(c + 0) * NCLS + 0] + v.y * wc[(c + 1) * NCLS + 0] +
               v.z * wc[(c + 2) * NCLS + 0] + v.w * wc[(c + 3) * NCLS + 0];
    float s1 = v.x * wc[(c + 0) * NCLS + 1] + v.y * wc[(c + 1) * NCLS + 1] +
               v.z * wc[(c + 2) * NCLS + 1] + v.w * wc[(c + 3) * NCLS + 1];
#pragma unroll
    for (int o = 16; o > 0; o >>= 1) {
        s0 += __shfl_xor_sync(0xffffffffu, s0, o);
        s1 += __shfl_xor_sync(0xffffffffu, s1, o);
    }
    if (lane == 0) {
        logits[g * NCLS + 0] = s0 + bc[0];
        logits[g * NCLS + 1] = s1 + bc[1];
    }
}

// ---------------- launch ----------------
extern "C" void kernel_launch(void* const* d_in, const int* in_sizes, int n_in,
                              void* d_out, int out_size) {
    const float* x     = (const float*)d_in[0];
    const int*   ei    = (const int*)d_in[1];
    const int*   batch = (const int*)d_in[2];
    const float* w1l = (const float*)d_in[3];
    const float* w1r = (const float*)d_in[4];
    const float* b1  = (const float*)d_in[5];
    const float* g1  = (const float*)d_in[6];
    const float* be1 = (const float*)d_in[7];
    const float* w2l = (const float*)d_in[8];
    const float* w2r = (const float*)d_in[9];
    const float* b2  = (const float*)d_in[10];
    const float* g2  = (const float*)d_in[11];
    const float* be2 = (const float*)d_in[12];
    const float* w3l = (const float*)d_in[13];
    const float* w3r = (const float*)d_in[14];
    const float* b3  = (const float*)d_in[15];
    const float* g3  = (const float*)d_in[16];
    const float* be3 = (const float*)d_in[17];
    const float* wc  = (const float*)d_in[18];
    const float* bc  = (const float*)d_in[19];

    const int E = in_sizes[1] / 2;

    float* out    = (float*)d_out;
    float* logits = out;
    float* h3     = out + (size_t)N_GRAPHS * NCLS;
    float* avg    = h3 + (size_t)N_NODES * FC;

    float *p_h1 = nullptr, *p_h2 = nullptr;
    cudaGetSymbolAddress((void**)&p_h1, g_h1);
    cudaGetSymbolAddress((void**)&p_h2, g_h2);

    cudaFuncSetAttribute(sage_mma_kernel<false, false>,
                         cudaFuncAttributeMaxDynamicSharedMemorySize, SM_TOTAL);
    cudaFuncSetAttribute(sage_mma_kernel<true, false>,
                         cudaFuncAttributeMaxDynamicSharedMemorySize, SM_TOTAL);
    cudaFuncSetAttribute(sage_mma_kernel<true, true>,
                         cudaFuncAttributeMaxDynamicSharedMemorySize, SM_TOTAL);

    const int TC_BLKS = NBLK;  // 391
    const int NODE_WARP_BLKS = (int)(((size_t)N_NODES * 32 + 255) / 256);
    const int DP_THREADS = (E > 3 * 32768) ? E : 3 * 32768;
    const int EDGE_BLKS = (E + 255) / 256;

    // CSR build fused with weight prep (g_cnt is zero on entry; scan re-zeroes it)
    degree_prep_kernel<<<(DP_THREADS + 255) / 256, 256>>>(
        ei, E, w1l, w1r, w2l, w2r, w3l, w3r);
    scan_kernel<<<1, 1024>>>();
    csr_fill_kernel<<<EDGE_BLKS, 256>>>(ei, E);

    // layer 1
    gather_kernel<<<NODE_WARP_BLKS, 256>>>(x);
    sage_mma_kernel<false, false><<<TC_BLKS, 256, SM_TOTAL>>>(
        x, b1, g1, be1, p_h1, batch, 0);

    // layer 2 (residual)
    gather_kernel<<<NODE_WARP_BLKS, 256>>>(p_h1);
    sage_mma_kernel<true, false><<<TC_BLKS, 256, SM_TOTAL>>>(
        p_h1, b2, g2, be2, p_h2, batch, 1);

    // layer 3 (residual + pool) -> h3 straight into d_out
    gather_kernel<<<NODE_WARP_BLKS, 256>>>(p_h2);
    sage_mma_kernel<true, true><<<TC_BLKS, 256, SM_TOTAL>>>(
        p_h2, b3, g3, be3, h3, batch, 2);

    pool_finalize_kernel<<<N_GRAPHS, 32>>>(wc, bc, logits, avg);
}

// round 16
// speedup vs baseline: 1.3758x; 1.0112x over previous
#include <cuda_runtime.h>
#include <cuda_fp16.h>
#include <math.h>
#include <stdint.h>

#define N_NODES 50000
#define N_GRAPHS 512
#define FC 128
#define NCLS 2
#define EMAX 2000000
#define NBLK 391   // ceil(N_NODES/128)

// ---------------- scratch (device globals; no allocs allowed) ----------------
// Self-cleaning invariant: g_cnt, g_psum, g_pcnt are zero at entry of every
// kernel_launch call (zero-initialized at load; re-zeroed by their consumers).
__device__ float g_h1[(size_t)N_NODES * FC];
__device__ float g_h2[(size_t)N_NODES * FC];
// agg stored as pre-swizzled fp16 SMEM images: [NBLK][2 chunks][8192 half]
__device__ __half g_agb[(size_t)NBLK * 2 * 8192];
__device__ int   g_cnt[N_NODES];
__device__ int   g_off[N_NODES + 1];
__device__ int   g_cur[N_NODES];
__device__ int   g_csr[EMAX];
__device__ float g_psum[N_GRAPHS * FC];
__device__ int   g_pcnt[N_GRAPHS];
// pre-transposed fp16, pre-swizzled weights: [3 layers][4 chunks][8192]
__device__ __half g_bt[3 * 4 * 8192];

#define SWZ128(b) ((b) ^ (((b) >> 3) & 0x70))

__device__ __forceinline__ uint32_t smem_to_u32(const void* p) {
    uint32_t a;
    asm("{ .reg .u64 t; cvta.to.shared.u64 t, %1; cvt.u32.u64 %0, t; }" : "=r"(a) : "l"(p));
    return a;
}
__device__ __forceinline__ void ldsm4(uint32_t& r0, uint32_t& r1, uint32_t& r2, uint32_t& r3,
                                      uint32_t addr) {
    asm volatile("ldmatrix.sync.aligned.m8n8.x4.shared.b16 {%0,%1,%2,%3}, [%4];"
                 : "=r"(r0), "=r"(r1), "=r"(r2), "=r"(r3) : "r"(addr));
}
__device__ __forceinline__ void mma16816(float* d, const uint32_t* a, uint32_t b0, uint32_t b1) {
    asm volatile(
        "mma.sync.aligned.m16n8k16.row.col.f32.f16.f16.f32 "
        "{%0,%1,%2,%3}, {%4,%5,%6,%7}, {%8,%9}, {%0,%1,%2,%3};"
        : "+f"(d[0]), "+f"(d[1]), "+f"(d[2]), "+f"(d[3])
        : "r"(a[0]), "r"(a[1]), "r"(a[2]), "r"(a[3]), "r"(b0), "r"(b1));
}

// ---------------- degree + weight prep (fused; prep covers first 98304 threads)
__global__ void degree_prep_kernel(
    const int* __restrict__ ei, int E,
    const float* __restrict__ w1l, const float* __restrict__ w1r,
    const float* __restrict__ w2l, const float* __restrict__ w2r,
    const float* __restrict__ w3l, const float* __restrict__ w3r)
{
    int i = blockIdx.x * blockDim.x + threadIdx.x;
    if (i < E) atomicAdd(&g_cnt[ei[E + i]], 1);
    if (i < 3 * 32768) {
        int layer = i >> 15;
        int li = i & 32767;
        int n = li >> 8, k = li & 255;
        const float* wl = (layer == 0) ? w1l : (layer == 1) ? w2l : w3l;
        const float* wr = (layer == 0) ? w1r : (layer == 1) ? w2r : w3r;
        float w = (k < 128) ? wl[k * FC + n] : wr[(k - 128) * FC + n];
        int chunk = k >> 6, kk = k & 63;
        int swz = SWZ128(n * 128 + kk * 2);
        g_bt[layer * 32768 + chunk * 8192 + (swz >> 1)] = __float2half_rn(w);
    }
}

// ---------------- exclusive scan over g_cnt -> g_off/g_cur; re-zeroes g_cnt ----
__global__ void __launch_bounds__(1024) scan_kernel() {
    __shared__ int wsum[32];
    __shared__ int s_carry;
    const int tid = threadIdx.x, lane = tid & 31, wid = tid >> 5;
    if (tid == 0) s_carry = 0;
    __syncthreads();
    for (int base = 0; base < N_NODES; base += 4096) {
        int i0 = base + tid * 4;
        int4 c = make_int4(0, 0, 0, 0);
        if (i0 + 3 < N_NODES) c = *reinterpret_cast<int4*>(&g_cnt[i0]);
        int t1 = c.x + c.y;
        int t2 = t1 + c.z;
        int tot = t2 + c.w;
        int v = tot;
#pragma unroll
        for (int o = 1; o < 32; o <<= 1) {
            int t = __shfl_up_sync(0xffffffffu, v, o);
            if (lane >= o) v += t;
        }
        if (lane == 31) wsum[wid] = v;
        __syncthreads();
        if (wid == 0) {
            int s = wsum[lane];
            int so = s;
#pragma unroll
            for (int o = 1; o < 32; o <<= 1) {
                int t = __shfl_up_sync(0xffffffffu, s, o);
                if (lane >= o) s += t;
            }
            wsum[lane] = s - so;
        }
        __syncthreads();
        int incl = v + wsum[wid];
        int carry = s_carry;
        if (i0 + 3 < N_NODES) {
            int e0 = carry + incl - tot;
            int4 off = make_int4(e0, e0 + c.x, e0 + t1, e0 + t2);
            *reinterpret_cast<int4*>(&g_off[i0]) = off;
            *reinterpret_cast<int4*>(&g_cur[i0]) = off;
            *reinterpret_cast<int4*>(&g_cnt[i0]) = make_int4(0, 0, 0, 0);  // self-clean
        }
        __syncthreads();
        if (tid == 1023) s_carry = carry + incl;
        __syncthreads();
    }
    if (tid == 0) g_off[N_NODES] = s_carry;
}

__global__ void csr_fill_kernel(const int* __restrict__ ei, int E) {
    int e = blockIdx.x * blockDim.x + threadIdx.x;
    if (e >= E) return;
    int dst = __ldg(&ei[E + e]);
    int pos = atomicAdd(&g_cur[dst], 1);
    g_csr[pos] = __ldg(&ei[e]);
}

// ---------------- gather: mean over neighbors (warp/node); writes fp16
//                  pre-swizzled agg images directly -------------------------
__global__ void __launch_bounds__(256) gather_kernel(const float* __restrict__ x) {
    int w = (blockIdx.x * blockDim.x + threadIdx.x) >> 5;
    int lane = threadIdx.x & 31;
    if (w >= N_NODES) return;
    const int beg = g_off[w];
    const int end = g_off[w + 1];
    float4 a0 = make_float4(0.f, 0.f, 0.f, 0.f);
    float4 a1 = make_float4(0.f, 0.f, 0.f, 0.f);
    for (int base = beg; base < end; base += 32) {
        int idx = base + lane;
        int si = (idx < end) ? g_csr[idx] : 0;
        int m = end - base;
        if (m >= 32) {
#pragma unroll 4
            for (int j = 0; j < 32; j += 2) {
                int s0 = __shfl_sync(0xffffffffu, si, j);
                int s1 = __shfl_sync(0xffffffffu, si, j + 1);
                float4 v0 = __ldg(reinterpret_cast<const float4*>(x + (size_t)s0 * FC) + lane);
                float4 v1 = __ldg(reinterpret_cast<const float4*>(x + (size_t)s1 * FC) + lane);
                a0.x += v0.x; a0.y += v0.y; a0.z += v0.z; a0.w += v0.w;
                a1.x += v1.x; a1.y += v1.y; a1.z += v1.z; a1.w += v1.w;
            }
        } else {
            int j = 0;
            for (; j + 1 < m; j += 2) {
                int s0 = __shfl_sync(0xffffffffu, si, j);
                int s1 = __shfl_sync(0xffffffffu, si, j + 1);
                float4 v0 = __ldg(reinterpret_cast<const float4*>(x + (size_t)s0 * FC) + lane);
                float4 v1 = __ldg(reinterpret_cast<const float4*>(x + (size_t)s1 * FC) + lane);
                a0.x += v0.x; a0.y += v0.y; a0.z += v0.z; a0.w += v0.w;
                a1.x += v1.x; a1.y += v1.y; a1.z += v1.z; a1.w += v1.w;
            }
            if (j < m) {
                int s0 = __shfl_sync(0xffffffffu, si, j);
                float4 v0 = __ldg(reinterpret_cast<const float4*>(x + (size_t)s0 * FC) + lane);
                a0.x += v0.x; a0.y += v0.y; a0.z += v0.z; a0.w += v0.w;
            }
        }
    }
    float inv = 1.f / fmaxf((float)(end - beg), 1.f);
    float v0 = (a0.x + a1.x) * inv;
    float v1 = (a0.y + a1.y) * inv;
    float v2 = (a0.z + a1.z) * inv;
    float v3 = (a0.w + a1.w) * inv;
    __half2 hh[2] = {__floats2half2_rn(v0, v1), __floats2half2_rn(v2, v3)};
    int blk = w >> 7, r = w & 127;
    int c = lane >> 4;              // chunk (cols 0-63 / 64-127)
    int kk = (lane & 15) * 4;       // col within chunk
    int swz = SWZ128(r * 128 + kk * 2);
    size_t img = ((size_t)blk * 2 + c) * 16384;  // bytes
    *reinterpret_cast<uint2*>(reinterpret_cast<char*>(g_agb) + img + swz) =
        *reinterpret_cast<uint2*>(hh);
}

// ---------------- tensor-core fused layer (single-pass fp16, double-buffered) -
#define SM_AB(i)  ((i) * 16384)
#define SM_BB(i)  (32768 + (i) * 16384)
#define SM_PS  65536
#define SM_PQ  (SM_PS + 1024)
#define SM_TOTAL (SM_PQ + 1024)   // 67584

template <bool RESID, bool POOL>
__global__ void __launch_bounds__(256) sage_mma_kernel(
    const float* __restrict__ xin,
    const float* __restrict__ bias, const float* __restrict__ gam,
    const float* __restrict__ bet,
    float* __restrict__ hout,
    const int* __restrict__ batch,
    int layer)
{
    extern __shared__ char smem[];
    const uint32_t sb = smem_to_u32(smem);
    const int tid = threadIdx.x;
    const int lane = tid & 31;
    const int wid = tid >> 5;
    const int wm = wid & 3;
    const int wn = wid >> 2;
    const int row0 = blockIdx.x * 128;

    float d[2][8][4];
#pragma unroll
    for (int i = 0; i < 2; i++)
#pragma unroll
        for (int j = 0; j < 8; j++)
#pragma unroll
            for (int t = 0; t < 4; t++) d[i][j][t] = 0.f;

    const int lm = lane >> 3, lr = lane & 7;
    int a_rowb[2];
#pragma unroll
    for (int mi = 0; mi < 2; mi++)
        a_rowb[mi] = (wm * 32 + mi * 16 + (lm & 1) * 8 + lr) * 128 + (lm >> 1) * 16;
    int b_rowb[4];
#pragma unroll
    for (int np = 0; np < 4; np++)
        b_rowb[np] = (wn * 64 + np * 16 + (lm >> 1) * 8 + lr) * 128 + (lm & 1) * 16;

    const __half* bt = g_bt + layer * 32768;

    auto load_chunk = [&](int chunk, int buf) {
        char* abuf = smem + SM_AB(buf);
        if (chunk < 2) {
            // agg chunk: straight copy of pre-swizzled fp16 image
            const uint4* ag = reinterpret_cast<const uint4*>(
                g_agb + ((size_t)blockIdx.x * 2 + chunk) * 8192);
            uint4* da = reinterpret_cast<uint4*>(abuf);
#pragma unroll
            for (int it = 0; it < 4; it++) {
                int i = it * 256 + tid;
                da[i] = __ldg(ag + i);
            }
        } else {
            // xin chunk: load fp32, convert to fp16, swizzle
            const int kofs = (chunk & 1) * 64;
#pragma unroll
            for (int it = 0; it < 4; it++) {
                int idx = it * 256 + tid;       // 0..1023
                int r = idx >> 3;
                int kk0 = (idx & 7) * 8;
                int gr = row0 + r;
                float4 fa = make_float4(0.f, 0.f, 0.f, 0.f), fb = fa;
                if (gr < N_NODES) {
                    const float4* p = reinterpret_cast<const float4*>(
                        xin + (size_t)gr * FC + kofs + kk0);
                    fa = p[0]; fb = p[1];
                }
                __half2 hh[4];
                hh[0] = __floats2half2_rn(fa.x, fa.y);
                hh[1] = __floats2half2_rn(fa.z, fa.w);
                hh[2] = __floats2half2_rn(fb.x, fb.y);
                hh[3] = __floats2half2_rn(fb.z, fb.w);
                int swz = SWZ128(r * 128 + kk0 * 2);
                *reinterpret_cast<uint4*>(abuf + swz) = *reinterpret_cast<uint4*>(hh);
            }
        }
        // B chunk copy
        const uint4* bsrc = reinterpret_cast<const uint4*>(bt + chunk * 8192);
        uint4* db = reinterpret_cast<uint4*>(smem + SM_BB(buf));
#pragma unroll
        for (int it = 0; it < 4; it++) {
            int i = it * 256 + tid;
            db[i] = __ldg(bsrc + i);
        }
    };

    load_chunk(0, 0);
    __syncthreads();

    for (int c = 0; c < 4; c++) {
        // prefetch next chunk into the other buffer (overlaps with mma below)
        if (c < 3) load_chunk(c + 1, (c + 1) & 1);

        const uint32_t aB = sb + SM_AB(c & 1);
        const uint32_t bB = sb + SM_BB(c & 1);
#pragma unroll
        for (int ks = 0; ks < 4; ks++) {
            uint32_t ar[2][4];
#pragma unroll
            for (int mi = 0; mi < 2; mi++) {
                uint32_t off = SWZ128(a_rowb[mi] + ks * 32);
                ldsm4(ar[mi][0], ar[mi][1], ar[mi][2], ar[mi][3], aB + off);
            }
#pragma unroll
            for (int np = 0; np < 4; np++) {
                uint32_t off = SWZ128(b_rowb[np] + ks * 32);
                uint32_t b0, b1, b2, b3;
                ldsm4(b0, b1, b2, b3, bB + off);
#pragma unroll
                for (int mi = 0; mi < 2; mi++) {
                    mma16816(d[mi][np * 2 + 0], ar[mi], b0, b1);
                    mma16816(d[mi][np * 2 + 1], ar[mi], b2, b3);
                }
            }
        }
        __syncthreads();
    }

    // ---------- epilogue: bias, relu, residual, LayerNorm (+ pool) ----------
    const int cb = wn * 64 + (lane & 3) * 2;
    float2 bb[8];
#pragma unroll
    for (int ni = 0; ni < 8; ni++)
        bb[ni] = __ldg(reinterpret_cast<const float2*>(bias + cb + ni * 8));

    float s[2][2] = {{0.f, 0.f}, {0.f, 0.f}};
    float q[2][2] = {{0.f, 0.f}, {0.f, 0.f}};
#pragma unroll
    for (int mi = 0; mi < 2; mi++) {
#pragma unroll
        for (int z = 0; z < 2; z++) {
            int rl = wm * 32 + mi * 16 + z * 8 + (lane >> 2);
            int gr = row0 + rl;
            bool valid = gr < N_NODES;
#pragma unroll
            for (int ni = 0; ni < 8; ni++) {
                float2 rv = make_float2(0.f, 0.f);
                if (RESID && valid)
                    rv = *reinterpret_cast<const float2*>(xin + (size_t)gr * FC + cb + ni * 8);
                float v0 = fmaxf(d[mi][ni][z * 2 + 0] + bb[ni].x, 0.f) + rv.x;
                float v1 = fmaxf(d[mi][ni][z * 2 + 1] + bb[ni].y, 0.f) + rv.y;
                s[mi][z] += v0 + v1;
                q[mi][z] += v0 * v0 + v1 * v1;
                d[mi][ni][z * 2 + 0] = v0;
                d[mi][ni][z * 2 + 1] = v1;
            }
        }
    }
    float* ps = reinterpret_cast<float*>(smem + SM_PS);
    float* pq = reinterpret_cast<float*>(smem + SM_PQ);
#pragma unroll
    for (int mi = 0; mi < 2; mi++) {
#pragma unroll
        for (int z = 0; z < 2; z++) {
            float ss = s[mi][z], qq = q[mi][z];
            ss += __shfl_xor_sync(0xffffffffu, ss, 1);
            ss += __shfl_xor_sync(0xffffffffu, ss, 2);
            qq += __shfl_xor_sync(0xffffffffu, qq, 1);
            qq += __shfl_xor_sync(0xffffffffu, qq, 2);
            if ((lane & 3) == 0) {
                int rl = wm * 32 + mi * 16 + z * 8 + (lane >> 2);
                ps[wn * 128 + rl] = ss;
                pq[wn * 128 + rl] = qq;
            }
        }
    }
    __syncthreads();
#pragma unroll
    for (int mi = 0; mi < 2; mi++) {
#pragma unroll
        for (int z = 0; z < 2; z++) {
            int rl = wm * 32 + mi * 16 + z * 8 + (lane >> 2);
            int gr = row0 + rl;
            if (gr >= N_NODES) continue;
            float S = ps[rl] + ps[128 + rl];
            float Q = pq[rl] + pq[128 + rl];
            float mean = S * (1.f / 128.f);
            float var = Q * (1.f / 128.f) - mean * mean;
            float rs = rsqrtf(var + 1e-5f);
            int bgr = POOL ? __ldg(&batch[gr]) : 0;
#pragma unroll
            for (int ni = 0; ni < 8; ni++) {
                float2 g2 = __ldg(reinterpret_cast<const float2*>(gam + cb + ni * 8));
                float2 e2 = __ldg(reinterpret_cast<const float2*>(bet + cb + ni * 8));
                float2 o2;
                o2.x = (d[mi][ni][z * 2 + 0] - mean) * rs * g2.x + e2.x;
                o2.y = (d[mi][ni][z * 2 + 1] - mean) * rs * g2.y + e2.y;
                *reinterpret_cast<float2*>(hout + (size_t)gr * FC + cb + ni * 8) = o2;
                if (POOL) {
                    atomicAdd(&g_psum[bgr * FC + cb + ni * 8], o2.x);
                    atomicAdd(&g_psum[bgr * FC + cb + ni * 8 + 1], o2.y);
                }
            }
            if (POOL && wn == 0 && (lane & 3) == 0)
                atomicAdd(&g_pcnt[bgr], 1);
        }
    }
}

// ---------------- finalize: avg + classifier; self-cleans g_psum/g_pcnt --------
__global__ void pool_finalize_kernel(const float* __restrict__ wc, const float* __restrict__ bc,
                                     float* __restrict__ logits, float* __restrict__ avg_out) {
    int g = blockIdx.x;
    int lane = threadIdx.x;  // blockDim = 32
    float inv = 1.f / fmaxf((float)g_pcnt[g], 1.f);
    float4 v = *reinterpret_cast<const float4*>(g_psum + g * FC + lane * 4);
    *reinterpret_cast<float4*>(g_psum + g * FC + lane * 4) = make_float4(0.f, 0.f, 0.f, 0.f);
    if (lane == 0) g_pcnt[g] = 0;
    v.x *= inv; v.y *= inv; v.z *= inv; v.w *= inv;
    *reinterpret_cast<float4*>(avg_out + (size_t)g * FC + lane * 4) = v;
    int c = lane * 4;
    float s0 = v.x * wc[(c + 0) * NCLS + 0] + v.y * wc[(c + 1) * NCLS + 0] +
               v.z * wc[(c + 2) * NCLS + 0] + v.w * wc[(c + 3) * NCLS + 0];
    float s1 = v.x * wc[(c + 0) * NCLS + 1] + v.y * wc[(c + 1) * NCLS + 1] +
               v.z * wc[(c + 2) * NCLS + 1] + v.w * wc[(c + 3) * NCLS + 1];
#pragma unroll
    for (int o = 16; o > 0; o >>= 1) {
        s0 += __shfl_xor_sync(0xffffffffu, s0, o);
        s1 += __shfl_xor_sync(0xffffffffu, s1, o);
    }
    if (lane == 0) {
        logits[g * NCLS + 0] = s0 + bc[0];
        logits[g * NCLS + 1] = s1 + bc[1];
    }
}

// ---------------- launch ----------------
extern "C" void kernel_launch(void* const* d_in, const int* in_sizes, int n_in,
                              void* d_out, int out_size) {
    const float* x     = (const float*)d_in[0];
    const int*   ei    = (const int*)d_in[1];
    const int*   batch = (const int*)d_in[2];
    const float* w1l = (const float*)d_in[3];
    const float* w1r = (const float*)d_in[4];
    const float* b1  = (const float*)d_in[5];
    const float* g1  = (const float*)d_in[6];
    const float* be1 = (const float*)d_in[7];
    const float* w2l = (const float*)d_in[8];
    const float* w2r = (const float*)d_in[9];
    const float* b2  = (const float*)d_in[10];
    const float* g2  = (const float*)d_in[11];
    const float* be2 = (const float*)d_in[12];
    const float* w3l = (const float*)d_in[13];
    const float* w3r = (const float*)d_in[14];
    const float* b3  = (const float*)d_in[15];
    const float* g3  = (const float*)d_in[16];
    const float* be3 = (const float*)d_in[17];
    const float* wc  = (const float*)d_in[18];
    const float* bc  = (const float*)d_in[19];

    const int E = in_sizes[1] / 2;

    float* out    = (float*)d_out;
    float* logits = out;
    float* h3     = out + (size_t)N_GRAPHS * NCLS;
    float* avg    = h3 + (size_t)N_NODES * FC;

    float *p_h1 = nullptr, *p_h2 = nullptr;
    cudaGetSymbolAddress((void**)&p_h1, g_h1);
    cudaGetSymbolAddress((void**)&p_h2, g_h2);

    cudaFuncSetAttribute(sage_mma_kernel<false, false>,
                         cudaFuncAttributeMaxDynamicSharedMemorySize, SM_TOTAL);
    cudaFuncSetAttribute(sage_mma_kernel<true, false>,
                         cudaFuncAttributeMaxDynamicSharedMemorySize, SM_TOTAL);
    cudaFuncSetAttribute(sage_mma_kernel<true, true>,
                         cudaFuncAttributeMaxDynamicSharedMemorySize, SM_TOTAL);

    const int TC_BLKS = NBLK;  // 391
    const int NODE_WARP_BLKS = (int)(((size_t)N_NODES * 32 + 255) / 256);
    const int DP_THREADS = (E > 3 * 32768) ? E : 3 * 32768;
    const int EDGE_BLKS = (E + 255) / 256;

    // CSR build fused with weight prep (g_cnt is zero on entry; scan re-zeroes it)
    degree_prep_kernel<<<(DP_THREADS + 255) / 256, 256>>>(
        ei, E, w1l, w1r, w2l, w2r, w3l, w3r);
    scan_kernel<<<1, 1024>>>();
    csr_fill_kernel<<<EDGE_BLKS, 256>>>(ei, E);

    // layer 1
    gather_kernel<<<NODE_WARP_BLKS, 256>>>(x);
    sage_mma_kernel<false, false><<<TC_BLKS, 256, SM_TOTAL>>>(
        x, b1, g1, be1, p_h1, batch, 0);

    // layer 2 (residual)
    gather_kernel<<<NODE_WARP_BLKS, 256>>>(p_h1);
    sage_mma_kernel<true, false><<<TC_BLKS, 256, SM_TOTAL>>>(
        p_h1, b2, g2, be2, p_h2, batch, 1);

    // layer 3 (residual + pool) -> h3 straight into d_out
    gather_kernel<<<NODE_WARP_BLKS, 256>>>(p_h2);
    sage_mma_kernel<true, true><<<TC_BLKS, 256, SM_TOTAL>>>(
        p_h2, b3, g3, be3, h3, batch, 2);

    pool_finalize_kernel<<<N_GRAPHS, 32>>>(wc, bc, logits, avg);
}